// round 6
// baseline (speedup 1.0000x reference)
#include <cuda_runtime.h>
#include <math.h>
#include <stdint.h>

#define Bc 4
#define Sc 1024
#define Dc 512
#define Hc 8
#define DHc 64
#define DIc 2048
#define Lc 12
#define Vc 10000
#define M_ROWS (Bc*Sc)   /* 4096 */
#define QKVSTR (3*Dc)    /* 1536 */

// ---------------- scratch (no allocations allowed) ----------------
__device__ float g_h   [M_ROWS*Dc];      // fp32 residual stream
__device__ float g_ht  [M_ROWS*Dc];      // tf32 bits, k-permuted (GEMM A)
__device__ float g_qkv [M_ROWS*QKVSTR];  // tf32 bits, unpermuted (attn operands)
__device__ float g_aot [M_ROWS*Dc];      // tf32 bits, k-permuted (attn out -> AO gemm A)
__device__ float g_tmp [M_ROWS*Dc];
__device__ float g_fft [M_ROWS*DIc];     // tf32 bits, k-permuted (FF1 out -> FF2 A)
// tf32-preconverted + k-permuted weights
__device__ float g_wqkv[Lc*QKVSTR*Dc];
__device__ float g_wo_t[Lc*Dc*Dc];
__device__ float g_w1_t[Lc*DIc*Dc];
__device__ float g_w2_t[Lc*Dc*DIc];
__device__ float g_we_t[Vc*Dc];

// ---------------- helpers ----------------------------------------------------
__device__ __forceinline__ uint32_t f2tf32(float f) {
    uint32_t r;
    asm("cvt.rna.tf32.f32 %0, %1;" : "=r"(r) : "f"(f));
    return r;
}
// k-permutation within 8-blocks: fragment pair (k, k+4) -> adjacent (2k, 2k+1)
__device__ __forceinline__ int permk(int c) {
    return (c & ~7) | ((c & 3) << 1) | ((c >> 2) & 1);
}
__device__ __forceinline__ int ipermk(int c) {   // inverse
    return (c & ~7) | ((c >> 1) & 3) | ((c & 1) << 2);
}

__device__ __forceinline__ void cp16(void* smem, const void* g, int srcBytes) {
    uint32_t s = (uint32_t)__cvta_generic_to_shared(smem);
    asm volatile("cp.async.cg.shared.global [%0], [%1], 16, %2;\n"
                 :: "r"(s), "l"(g), "r"(srcBytes));
}

__device__ __forceinline__ void mma_tf32(float c[4],
    uint32_t a0, uint32_t a1, uint32_t a2, uint32_t a3,
    uint32_t b0, uint32_t b1)
{
    asm volatile(
        "mma.sync.aligned.m16n8k8.row.col.f32.tf32.tf32.f32 "
        "{%0,%1,%2,%3}, {%4,%5,%6,%7}, {%8,%9}, {%0,%1,%2,%3};"
        : "+f"(c[0]), "+f"(c[1]), "+f"(c[2]), "+f"(c[3])
        : "r"(a0), "r"(a1), "r"(a2), "r"(a3), "r"(b0), "r"(b1));
}

// ---------------- weight preconversion (tf32 + k-permute) --------------------
__global__ void pack_qkv_w(const float* __restrict__ Wq, const float* __restrict__ Wkv,
                           float* __restrict__ dst) {
    int i = blockIdx.x * blockDim.x + threadIdx.x;
    if (i >= Lc * QKVSTR * Dc) return;
    int kk = i % Dc;
    int r  = (i / Dc) % QKVSTR;
    int l  = i / (Dc * QKVSTR);
    int k  = ipermk(kk);
    float v;
    if (r < Dc) v = Wq[((size_t)l * Dc + r) * Dc + k] * 0.125f;
    else        v = Wkv[((size_t)l * 2 * Dc + (r - Dc)) * Dc + k];
    dst[i] = __uint_as_float(f2tf32(v));
}

// generic: rows all multiples of 8 so linear in-block permutation is valid
__global__ void pack_w(const float* __restrict__ src, float* __restrict__ dst, int n) {
    int i = blockIdx.x * blockDim.x + threadIdx.x;
    if (i < n) dst[i] = __uint_as_float(f2tf32(src[(i & ~7) | ipermk(i & 7)]));
}

// ---------------- embedding ----------------
__global__ void embed_kernel(const int* __restrict__ data,
                             const float* __restrict__ we,
                             const float* __restrict__ pe,
                             float* __restrict__ h, float* __restrict__ ht) {
    int i = blockIdx.x * blockDim.x + threadIdx.x;
    if (i >= M_ROWS * Dc) return;
    int d   = i % Dc;
    int row = i / Dc;
    int s   = row % Sc;
    int tok = data[row];
    float v = we[(size_t)tok * Dc + d] + pe[(size_t)s * Dc + d];
    h[i] = v;
    ht[(i & ~7) | permk(i & 7)] = __uint_as_float(f2tf32(v));
}

// ---------------- tf32 tensor-core GEMM --------------------------------------
// C[M,N] = A[M,K] @ W[N,K]^T. A and W are tf32 bits in k-permuted layout.
// outMode: 0 = fp32 out, 1 = tf32 bits out (unpermuted), 2 = tf32 bits out (k-permuted)
#define TBM 128
#define TBN 128
#define TBK 16
#define TPITCH 20

__global__ __launch_bounds__(256) void tgemm_kernel(
    const float* __restrict__ A, const float* __restrict__ W,
    const float* __restrict__ bias, const float* __restrict__ res,
    float* __restrict__ C, int M, int N, int K, int doRelu, int outMode)
{
    __shared__ __align__(16) float As[2][TBM][TPITCH];
    __shared__ __align__(16) float Bs[2][TBN][TPITCH];

    const int tid  = threadIdx.x;
    const int lane = tid & 31;
    const int warp = tid >> 5;
    const int wm   = warp >> 2;
    const int wn   = warp & 3;
    const int bm   = blockIdx.y * TBM;
    const int bn   = blockIdx.x * TBN;

    const int ldr = tid >> 2;
    const int kc  = (tid & 3) * 4;

    float acc[4][4][4];
    #pragma unroll
    for (int i = 0; i < 4; i++)
        #pragma unroll
        for (int j = 0; j < 4; j++)
            #pragma unroll
            for (int t = 0; t < 4; t++) acc[i][j][t] = 0.f;

    const int KT = K / TBK;

    {
        #pragma unroll
        for (int p = 0; p < 2; p++) {
            int r = ldr + p * 64;
            cp16(&As[0][r][kc], A + (size_t)(bm + r) * K + kc, 16);
        }
        #pragma unroll
        for (int p = 0; p < 2; p++) {
            int r  = ldr + p * 64;
            int gn = bn + r;
            int ok = (gn < N) ? 16 : 0;
            int gc = (gn < N) ? gn : (N - 1);
            cp16(&Bs[0][r][kc], W + (size_t)gc * K + kc, ok);
        }
        asm volatile("cp.async.commit_group;\n");
    }

    for (int t = 0; t < KT; t++) {
        asm volatile("cp.async.wait_group 0;\n");
        __syncthreads();

        if (t + 1 < KT) {
            int nb = (t + 1) & 1;
            int k0 = (t + 1) * TBK;
            #pragma unroll
            for (int p = 0; p < 2; p++) {
                int r = ldr + p * 64;
                cp16(&As[nb][r][kc], A + (size_t)(bm + r) * K + k0 + kc, 16);
            }
            #pragma unroll
            for (int p = 0; p < 2; p++) {
                int r  = ldr + p * 64;
                int gn = bn + r;
                int ok = (gn < N) ? 16 : 0;
                int gc = (gn < N) ? gn : (N - 1);
                cp16(&Bs[nb][r][kc], W + (size_t)gc * K + k0 + kc, ok);
            }
            asm volatile("cp.async.commit_group;\n");
        }

        const int buf = t & 1;
        const uint32_t* Au = (const uint32_t*)&As[buf][0][0];
        const uint32_t* Bu = (const uint32_t*)&Bs[buf][0][0];
        #pragma unroll
        for (int ks = 0; ks < 2; ks++) {
            const int colp = ks * 8 + 2 * (lane & 3);   // permuted pair base
            const int ra   = wm * 64 + (lane >> 2);
            const int rb   = wn * 32 + (lane >> 2);

            uint32_t af[4][4], bf[4][2];
            #pragma unroll
            for (int mi = 0; mi < 4; mi++) {
                uint2 p0 = *(const uint2*)&Au[(ra + mi * 16    ) * TPITCH + colp];
                uint2 p1 = *(const uint2*)&Au[(ra + mi * 16 + 8) * TPITCH + colp];
                af[mi][0] = p0.x; af[mi][1] = p1.x; af[mi][2] = p0.y; af[mi][3] = p1.y;
            }
            #pragma unroll
            for (int ni = 0; ni < 4; ni++) {
                uint2 q = *(const uint2*)&Bu[(rb + ni * 8) * TPITCH + colp];
                bf[ni][0] = q.x; bf[ni][1] = q.y;
            }
            #pragma unroll
            for (int mi = 0; mi < 4; mi++)
                #pragma unroll
                for (int ni = 0; ni < 4; ni++)
                    mma_tf32(acc[mi][ni], af[mi][0], af[mi][1], af[mi][2], af[mi][3],
                             bf[ni][0], bf[ni][1]);
        }
        __syncthreads();
    }

    const int lr = lane >> 2;
    const int lc = (lane & 3) * 2;
    #pragma unroll
    for (int mi = 0; mi < 4; mi++) {
        int r0 = bm + wm * 64 + mi * 16 + lr;
        #pragma unroll
        for (int ni = 0; ni < 4; ni++) {
            int c0 = bn + wn * 32 + ni * 8 + lc;
            if (c0 >= N) continue;
            float v0 = acc[mi][ni][0], v1 = acc[mi][ni][1];
            float v2 = acc[mi][ni][2], v3 = acc[mi][ni][3];
            if (bias) {
                float b0 = bias[c0], b1 = bias[c0 + 1];
                v0 += b0; v1 += b1; v2 += b0; v3 += b1;
            }
            if (res) {
                v0 += res[(size_t)r0 * N + c0];
                v1 += res[(size_t)r0 * N + c0 + 1];
                v2 += res[(size_t)(r0 + 8) * N + c0];
                v3 += res[(size_t)(r0 + 8) * N + c0 + 1];
            }
            if (doRelu) {
                v0 = fmaxf(v0, 0.f); v1 = fmaxf(v1, 0.f);
                v2 = fmaxf(v2, 0.f); v3 = fmaxf(v3, 0.f);
            }
            if (outMode == 0) {
                *(float2*)&C[(size_t)r0 * N + c0]       = make_float2(v0, v1);
                *(float2*)&C[(size_t)(r0 + 8) * N + c0] = make_float2(v2, v3);
            } else if (outMode == 1) {
                *(float2*)&C[(size_t)r0 * N + c0] =
                    make_float2(__uint_as_float(f2tf32(v0)), __uint_as_float(f2tf32(v1)));
                *(float2*)&C[(size_t)(r0 + 8) * N + c0] =
                    make_float2(__uint_as_float(f2tf32(v2)), __uint_as_float(f2tf32(v3)));
            } else {
                int cA = permk(c0), cB = permk(c0 + 1);
                C[(size_t)r0 * N + cA]       = __uint_as_float(f2tf32(v0));
                C[(size_t)r0 * N + cB]       = __uint_as_float(f2tf32(v1));
                C[(size_t)(r0 + 8) * N + cA] = __uint_as_float(f2tf32(v2));
                C[(size_t)(r0 + 8) * N + cB] = __uint_as_float(f2tf32(v3));
            }
        }
    }
}

// ---------------- tensor-core flash attention --------------------------------
// Q/K/V in fused qkv buffer (stride 1536), tf32 bits, Q pre-scaled.
// Output: tf32 bits, k-permuted (feeds AO gemm as A).
#define AP 68
#define FATTN_SMEM ((6 * 64 * AP) * 4)

extern __shared__ float dyn_smem[];

__global__ __launch_bounds__(128) void fattn_tc(
    const float* __restrict__ Q, const float* __restrict__ Kb,
    const float* __restrict__ Vb, float* __restrict__ O)
{
    float* Qs  = dyn_smem;
    float* Ks  = Qs + 64 * AP;
    float* Vk  = Ks + 2 * 64 * AP;
    float* Ss  = Vk + 2 * 64 * AP;

    const int qt = (gridDim.x - 1) - blockIdx.x;
    const int h  = blockIdx.y, b = blockIdx.z;
    const int q0 = qt * 64;
    const int tid  = threadIdx.x;
    const int lane = tid & 31;
    const int warp = tid >> 5;

    const int OST = Hc * DHc;           // 512

    const int r0  = warp * 16 + (lane >> 2);
    const int cq  = lane & 3;
    const int ls4 = lane >> 2;

    #pragma unroll
    for (int p = 0; p < 8; p++) {
        int c = tid + p * 128;
        int r = c >> 4, d4 = (c & 15) * 4;
        float4 v = *(const float4*)(Q + (size_t)(b * Sc + q0 + r) * QKVSTR + h * DHc + d4);
        *(float4*)&Qs[r * AP + d4] = v;
    }

    float o_acc[8][4];
    #pragma unroll
    for (int n = 0; n < 8; n++)
        #pragma unroll
        for (int t = 0; t < 4; t++) o_acc[n][t] = 0.f;
    float m0 = -1e30f, m1 = -1e30f, l0 = 0.f, l1 = 0.f;

    const int nt = qt + 1;
    const size_t kvrow0 = (size_t)(b * Sc) * QKVSTR + h * DHc;

    #pragma unroll
    for (int p = 0; p < 8; p++) {
        int c = tid + p * 128;
        int r = c >> 4, d4 = (c & 15) * 4;
        cp16(&Ks[r * AP + d4], Kb + kvrow0 + (size_t)r * QKVSTR + d4, 16);
        cp16(&Vk[r * AP + d4], Vb + kvrow0 + (size_t)r * QKVSTR + d4, 16);
    }
    asm volatile("cp.async.commit_group;\n");

    for (int kt = 0; kt < nt; kt++) {
        asm volatile("cp.async.wait_group 0;\n");
        __syncthreads();

        const int buf = kt & 1;
        if (kt + 1 < nt) {
            const int nb = buf ^ 1;
            const size_t base = kvrow0 + (size_t)(kt + 1) * 64 * QKVSTR;
            #pragma unroll
            for (int p = 0; p < 8; p++) {
                int c = tid + p * 128;
                int r = c >> 4, d4 = (c & 15) * 4;
                cp16(&Ks[nb * 64 * AP + r * AP + d4], Kb + base + (size_t)r * QKVSTR + d4, 16);
                cp16(&Vk[nb * 64 * AP + r * AP + d4], Vb + base + (size_t)r * QKVSTR + d4, 16);
            }
        }
        asm volatile("cp.async.commit_group;\n");

        const uint32_t* Qu = (const uint32_t*)Qs;
        const uint32_t* Ku = (const uint32_t*)(Ks + buf * 64 * AP);
        const uint32_t* Vu = (const uint32_t*)(Vk + buf * 64 * AP);
        uint32_t*       Pu = (uint32_t*)Ss;

        float sacc[8][4];
        #pragma unroll
        for (int n = 0; n < 8; n++)
            #pragma unroll
            for (int t = 0; t < 4; t++) sacc[n][t] = 0.f;

        #pragma unroll
        for (int k8 = 0; k8 < 8; k8++) {
            const int kcol = k8 * 8 + cq;
            uint32_t a0 = Qu[ r0      * AP + kcol];
            uint32_t a1 = Qu[(r0 + 8) * AP + kcol];
            uint32_t a2 = Qu[ r0      * AP + kcol + 4];
            uint32_t a3 = Qu[(r0 + 8) * AP + kcol + 4];
            #pragma unroll
            for (int n = 0; n < 8; n++) {
                const int nr = n * 8 + ls4;
                mma_tf32(sacc[n], a0, a1, a2, a3,
                         Ku[nr * AP + kcol], Ku[nr * AP + kcol + 4]);
            }
        }

        if (kt == qt) {
            #pragma unroll
            for (int n = 0; n < 8; n++) {
                const int c0 = n * 8 + cq * 2;
                if (c0     > r0)     sacc[n][0] = -1e30f;
                if (c0 + 1 > r0)     sacc[n][1] = -1e30f;
                if (c0     > r0 + 8) sacc[n][2] = -1e30f;
                if (c0 + 1 > r0 + 8) sacc[n][3] = -1e30f;
            }
        }

        float mx0 = -1e30f, mx1 = -1e30f;
        #pragma unroll
        for (int n = 0; n < 8; n++) {
            mx0 = fmaxf(mx0, fmaxf(sacc[n][0], sacc[n][1]));
            mx1 = fmaxf(mx1, fmaxf(sacc[n][2], sacc[n][3]));
        }
        mx0 = fmaxf(mx0, __shfl_xor_sync(0xffffffffu, mx0, 1));
        mx0 = fmaxf(mx0, __shfl_xor_sync(0xffffffffu, mx0, 2));
        mx1 = fmaxf(mx1, __shfl_xor_sync(0xffffffffu, mx1, 1));
        mx1 = fmaxf(mx1, __shfl_xor_sync(0xffffffffu, mx1, 2));

        const float mn0 = fmaxf(m0, mx0);
        const float mn1 = fmaxf(m1, mx1);
        const float cr0 = __expf(m0 - mn0);
        const float cr1 = __expf(m1 - mn1);
        float s0 = 0.f, s1 = 0.f;
        #pragma unroll
        for (int n = 0; n < 8; n++) {
            float p00 = __expf(sacc[n][0] - mn0);
            float p01 = __expf(sacc[n][1] - mn0);
            float p10 = __expf(sacc[n][2] - mn1);
            float p11 = __expf(sacc[n][3] - mn1);
            s0 += p00 + p01;
            s1 += p10 + p11;
            const int c0 = n * 8 + cq * 2;
            *(uint2*)&Pu[ r0      * AP + c0] = make_uint2(f2tf32(p00), f2tf32(p01));
            *(uint2*)&Pu[(r0 + 8) * AP + c0] = make_uint2(f2tf32(p10), f2tf32(p11));
        }
        s0 += __shfl_xor_sync(0xffffffffu, s0, 1);
        s0 += __shfl_xor_sync(0xffffffffu, s0, 2);
        s1 += __shfl_xor_sync(0xffffffffu, s1, 1);
        s1 += __shfl_xor_sync(0xffffffffu, s1, 2);

        l0 = l0 * cr0 + s0;  m0 = mn0;
        l1 = l1 * cr1 + s1;  m1 = mn1;
        #pragma unroll
        for (int n = 0; n < 8; n++) {
            o_acc[n][0] *= cr0; o_acc[n][1] *= cr0;
            o_acc[n][2] *= cr1; o_acc[n][3] *= cr1;
        }
        __syncwarp();

        #pragma unroll
        for (int k8 = 0; k8 < 8; k8++) {
            const int kcol = k8 * 8 + cq;
            uint32_t a0 = Pu[ r0      * AP + kcol];
            uint32_t a1 = Pu[(r0 + 8) * AP + kcol];
            uint32_t a2 = Pu[ r0      * AP + kcol + 4];
            uint32_t a3 = Pu[(r0 + 8) * AP + kcol + 4];
            #pragma unroll
            for (int n = 0; n < 8; n++) {
                const int nr = n * 8 + ls4;
                mma_tf32(o_acc[n], a0, a1, a2, a3,
                         Vu[kcol * AP + nr], Vu[(kcol + 4) * AP + nr]);
            }
        }
    }

    // epilogue: tf32 bits, k-permuted columns
    const float inv0 = 1.f / l0;
    const float inv1 = 1.f / l1;
    #pragma unroll
    for (int n = 0; n < 8; n++) {
        const int c0 = n * 8 + cq * 2;
        const int C0 = h * DHc + c0;
        const int cA = permk(C0), cB = permk(C0 + 1);
        size_t rowA = (size_t)(b * Sc + q0 + r0)     * OST;
        size_t rowB = (size_t)(b * Sc + q0 + r0 + 8) * OST;
        O[rowA + cA] = __uint_as_float(f2tf32(o_acc[n][0] * inv0));
        O[rowA + cB] = __uint_as_float(f2tf32(o_acc[n][1] * inv0));
        O[rowB + cA] = __uint_as_float(f2tf32(o_acc[n][2] * inv1));
        O[rowB + cB] = __uint_as_float(f2tf32(o_acc[n][3] * inv1));
    }
}

// ---------------- LayerNorm over D=512 (dual output: fp32 + permuted tf32) ---
__global__ void ln_kernel(const float* __restrict__ X, const float* __restrict__ g,
                          const float* __restrict__ bta, float* __restrict__ Y,
                          float* __restrict__ Yt) {
    int row = blockIdx.x;
    const float* x = X + (size_t)row * Dc;
    float* y  = Y  + (size_t)row * Dc;
    float* yt = Yt + (size_t)row * Dc;
    int tid = threadIdx.x;

    float v[4];
    float sum = 0.f;
    #pragma unroll
    for (int i = 0; i < 4; i++) { v[i] = x[tid + i*128]; sum += v[i]; }

    __shared__ float red[4];
    #pragma unroll
    for (int off = 16; off; off >>= 1) sum += __shfl_xor_sync(0xffffffffu, sum, off);
    if ((tid & 31) == 0) red[tid >> 5] = sum;
    __syncthreads();
    sum = red[0] + red[1] + red[2] + red[3];
    float mean = sum * (1.f / Dc);

    float sq = 0.f;
    #pragma unroll
    for (int i = 0; i < 4; i++) { float d = v[i] - mean; sq += d * d; }
    __shared__ float red2[4];
    #pragma unroll
    for (int off = 16; off; off >>= 1) sq += __shfl_xor_sync(0xffffffffu, sq, off);
    if ((tid & 31) == 0) red2[tid >> 5] = sq;
    __syncthreads();
    sq = red2[0] + red2[1] + red2[2] + red2[3];
    float rstd = rsqrtf(sq * (1.f / Dc) + 1e-5f);

    #pragma unroll
    for (int i = 0; i < 4; i++) {
        int d = tid + i*128;
        float o = (v[i] - mean) * rstd * g[d] + bta[d];
        y[d] = o;
        yt[(d & ~7) | permk(d & 7)] = __uint_as_float(f2tf32(o));
    }
}

// ---------------- launch ----------------------------------------------------
extern "C" void kernel_launch(void* const* d_in, const int* in_sizes, int n_in,
                              void* d_out, int out_size) {
    const int*   data = (const int*)  d_in[0];
    const float* we   = (const float*)d_in[1];
    const float* pe   = (const float*)d_in[2];
    const float* Wq   = (const float*)d_in[3];
    const float* Wkv  = (const float*)d_in[4];
    const float* Wo   = (const float*)d_in[5];
    const float* g1   = (const float*)d_in[6];
    const float* bl1  = (const float*)d_in[7];
    const float* W1   = (const float*)d_in[8];
    const float* bf1  = (const float*)d_in[9];
    const float* W2   = (const float*)d_in[10];
    const float* bf2  = (const float*)d_in[11];
    const float* g2   = (const float*)d_in[12];
    const float* bl2  = (const float*)d_in[13];
    const float* outb = (const float*)d_in[14];
    float* out = (float*)d_out;

    float *h, *ht, *qkv, *aot, *tmp, *fft;
    float *wqkv, *wo_t, *w1_t, *w2_t, *we_t;
    cudaGetSymbolAddress((void**)&h,    g_h);
    cudaGetSymbolAddress((void**)&ht,   g_ht);
    cudaGetSymbolAddress((void**)&qkv,  g_qkv);
    cudaGetSymbolAddress((void**)&aot,  g_aot);
    cudaGetSymbolAddress((void**)&tmp,  g_tmp);
    cudaGetSymbolAddress((void**)&fft,  g_fft);
    cudaGetSymbolAddress((void**)&wqkv, g_wqkv);
    cudaGetSymbolAddress((void**)&wo_t, g_wo_t);
    cudaGetSymbolAddress((void**)&w1_t, g_w1_t);
    cudaGetSymbolAddress((void**)&w2_t, g_w2_t);
    cudaGetSymbolAddress((void**)&we_t, g_we_t);

    cudaFuncSetAttribute(fattn_tc, cudaFuncAttributeMaxDynamicSharedMemorySize, FATTN_SMEM);

    // weight preconversion (tf32 bits, k-permuted)
    {
        int n;
        n = Lc * QKVSTR * Dc;  pack_qkv_w<<<(n + 255)/256, 256>>>(Wq, Wkv, wqkv);
        n = Lc * Dc * Dc;      pack_w<<<(n + 255)/256, 256>>>(Wo, wo_t, n);
        n = Lc * DIc * Dc;     pack_w<<<(n + 255)/256, 256>>>(W1, w1_t, n);
        n = Lc * Dc * DIc;     pack_w<<<(n + 255)/256, 256>>>(W2, w2_t, n);
        n = Vc * Dc;           pack_w<<<(n + 255)/256, 256>>>(we, we_t, n);
    }

    embed_kernel<<<(M_ROWS*Dc + 255)/256, 256>>>(data, we, pe, h, ht);

    dim3 gsD  (( Dc     + 127)/128, M_ROWS/128);
    dim3 gsQKV((QKVSTR  + 127)/128, M_ROWS/128);
    dim3 gsDI (( DIc    + 127)/128, M_ROWS/128);
    dim3 gsV  (( Vc     + 127)/128, M_ROWS/128);
    dim3 gsA  (Sc/64, Hc, Bc);

    for (int l = 0; l < Lc; l++) {
        tgemm_kernel<<<gsQKV, 256>>>(ht, wqkv + (size_t)l*QKVSTR*Dc, nullptr, nullptr,
                                     qkv, M_ROWS, QKVSTR, Dc, 0, 1);

        fattn_tc<<<gsA, 128, FATTN_SMEM>>>(qkv, qkv + Dc, qkv + 2*Dc, aot);

        tgemm_kernel<<<gsD, 256>>>(aot, wo_t + (size_t)l*Dc*Dc, nullptr, h, tmp,
                                   M_ROWS, Dc, Dc, 0, 0);
        ln_kernel<<<M_ROWS, 128>>>(tmp, g1 + (size_t)l*Dc, bl1 + (size_t)l*Dc, h, ht);

        tgemm_kernel<<<gsDI, 256>>>(ht, w1_t + (size_t)l*DIc*Dc, bf1 + (size_t)l*DIc, nullptr,
                                    fft, M_ROWS, DIc, Dc, 1, 2);
        tgemm_kernel<<<gsD, 256>>>(fft, w2_t + (size_t)l*Dc*DIc, bf2 + (size_t)l*Dc, h,
                                   tmp, M_ROWS, Dc, DIc, 0, 0);
        ln_kernel<<<M_ROWS, 128>>>(tmp, g2 + (size_t)l*Dc, bl2 + (size_t)l*Dc, h, ht);
    }

    tgemm_kernel<<<gsV, 256>>>(ht, we_t, outb, nullptr, out, M_ROWS, Vc, Dc, 0, 0);
}

// round 7
// speedup vs baseline: 1.0884x; 1.0884x over previous
#include <cuda_runtime.h>
#include <math.h>
#include <stdint.h>

#define Bc 4
#define Sc 1024
#define Dc 512
#define Hc 8
#define DHc 64
#define DIc 2048
#define Lc 12
#define Vc 10000
#define M_ROWS (Bc*Sc)   /* 4096 */
#define QKVSTR (3*Dc)    /* 1536 */

// ---------------- scratch (no allocations allowed) ----------------
__device__ float g_h   [M_ROWS*Dc];      // fp32 residual stream
__device__ float g_ht  [M_ROWS*Dc];      // tf32 bits (GEMM A operand)
__device__ float g_qkv [M_ROWS*QKVSTR];  // tf32 bits (attn operands)
__device__ float g_aot [M_ROWS*Dc];      // tf32 bits (attn out -> AO gemm A)
__device__ float g_tmp [M_ROWS*Dc];
__device__ float g_fft [M_ROWS*DIc];     // tf32 bits (FF1 out -> FF2 A)
// tf32-preconverted weights
__device__ float g_wqkv[Lc*QKVSTR*Dc];
__device__ float g_wo_t[Lc*Dc*Dc];
__device__ float g_w1_t[Lc*DIc*Dc];
__device__ float g_w2_t[Lc*Dc*DIc];
__device__ float g_we_t[Vc*Dc];

// ---------------- helpers ----------------------------------------------------
__device__ __forceinline__ uint32_t f2tf32(float f) {
    uint32_t r;
    asm("cvt.rna.tf32.f32 %0, %1;" : "=r"(r) : "f"(f));
    return r;
}

__device__ __forceinline__ void cp16(void* smem, const void* g, int srcBytes) {
    uint32_t s = (uint32_t)__cvta_generic_to_shared(smem);
    asm volatile("cp.async.cg.shared.global [%0], [%1], 16, %2;\n"
                 :: "r"(s), "l"(g), "r"(srcBytes));
}

__device__ __forceinline__ void mma_tf32(float c[4],
    uint32_t a0, uint32_t a1, uint32_t a2, uint32_t a3,
    uint32_t b0, uint32_t b1)
{
    asm volatile(
        "mma.sync.aligned.m16n8k8.row.col.f32.tf32.tf32.f32 "
        "{%0,%1,%2,%3}, {%4,%5,%6,%7}, {%8,%9}, {%0,%1,%2,%3};"
        : "+f"(c[0]), "+f"(c[1]), "+f"(c[2]), "+f"(c[3])
        : "r"(a0), "r"(a1), "r"(a2), "r"(a3), "r"(b0), "r"(b1));
}

// ---------------- weight preconversion (tf32 bits) ---------------------------
__global__ void pack_qkv_w(const float* __restrict__ Wq, const float* __restrict__ Wkv,
                           float* __restrict__ dst) {
    int i = blockIdx.x * blockDim.x + threadIdx.x;
    if (i >= Lc * QKVSTR * Dc) return;
    int c = i % Dc;
    int r = (i / Dc) % QKVSTR;
    int l = i / (Dc * QKVSTR);
    float v;
    if (r < Dc) v = Wq[((size_t)l * Dc + r) * Dc + c] * 0.125f;
    else        v = Wkv[((size_t)l * 2 * Dc + (r - Dc)) * Dc + c];
    dst[i] = __uint_as_float(f2tf32(v));
}

__global__ void cvt_w(const float* __restrict__ src, float* __restrict__ dst, int n) {
    int i = blockIdx.x * blockDim.x + threadIdx.x;
    if (i < n) dst[i] = __uint_as_float(f2tf32(src[i]));
}

// ---------------- embedding ----------------
__global__ void embed_kernel(const int* __restrict__ data,
                             const float* __restrict__ we,
                             const float* __restrict__ pe,
                             float* __restrict__ h, float* __restrict__ ht) {
    int i = blockIdx.x * blockDim.x + threadIdx.x;
    if (i >= M_ROWS * Dc) return;
    int d   = i % Dc;
    int row = i / Dc;
    int s   = row % Sc;
    int tok = data[row];
    float v = we[(size_t)tok * Dc + d] + pe[(size_t)s * Dc + d];
    h[i]  = v;
    ht[i] = __uint_as_float(f2tf32(v));
}

// ---------------- tf32 tensor-core GEMM --------------------------------------
// C[M,N] = A[M,K] @ W[N,K]^T. A and W are tf32 bits (plain layout).
// outMode: 0 = fp32 out, 1 = tf32 bits out
#define TBM 128
#define TBN 128
#define TBK 16
#define TPITCH 20

__global__ __launch_bounds__(256) void tgemm_kernel(
    const float* __restrict__ A, const float* __restrict__ W,
    const float* __restrict__ bias, const float* __restrict__ res,
    float* __restrict__ C, int M, int N, int K, int doRelu, int outMode)
{
    __shared__ __align__(16) float As[2][TBM][TPITCH];
    __shared__ __align__(16) float Bs[2][TBN][TPITCH];

    const int tid  = threadIdx.x;
    const int lane = tid & 31;
    const int warp = tid >> 5;
    const int wm   = warp >> 2;
    const int wn   = warp & 3;
    const int bm   = blockIdx.y * TBM;
    const int bn   = blockIdx.x * TBN;

    const int ldr = tid >> 2;
    const int kc  = (tid & 3) * 4;

    float acc[4][4][4];
    #pragma unroll
    for (int i = 0; i < 4; i++)
        #pragma unroll
        for (int j = 0; j < 4; j++)
            #pragma unroll
            for (int t = 0; t < 4; t++) acc[i][j][t] = 0.f;

    const int KT = K / TBK;

    {
        #pragma unroll
        for (int p = 0; p < 2; p++) {
            int r = ldr + p * 64;
            cp16(&As[0][r][kc], A + (size_t)(bm + r) * K + kc, 16);
        }
        #pragma unroll
        for (int p = 0; p < 2; p++) {
            int r  = ldr + p * 64;
            int gn = bn + r;
            int ok = (gn < N) ? 16 : 0;
            int gc = (gn < N) ? gn : (N - 1);
            cp16(&Bs[0][r][kc], W + (size_t)gc * K + kc, ok);
        }
        asm volatile("cp.async.commit_group;\n");
    }

    for (int t = 0; t < KT; t++) {
        asm volatile("cp.async.wait_group 0;\n");
        __syncthreads();

        if (t + 1 < KT) {
            int nb = (t + 1) & 1;
            int k0 = (t + 1) * TBK;
            #pragma unroll
            for (int p = 0; p < 2; p++) {
                int r = ldr + p * 64;
                cp16(&As[nb][r][kc], A + (size_t)(bm + r) * K + k0 + kc, 16);
            }
            #pragma unroll
            for (int p = 0; p < 2; p++) {
                int r  = ldr + p * 64;
                int gn = bn + r;
                int ok = (gn < N) ? 16 : 0;
                int gc = (gn < N) ? gn : (N - 1);
                cp16(&Bs[nb][r][kc], W + (size_t)gc * K + k0 + kc, ok);
            }
            asm volatile("cp.async.commit_group;\n");
        }

        const int buf = t & 1;
        const uint32_t* Au = (const uint32_t*)&As[buf][0][0];
        const uint32_t* Bu = (const uint32_t*)&Bs[buf][0][0];
        #pragma unroll
        for (int ks = 0; ks < 2; ks++) {
            const int col = ks * 8 + (lane & 3);
            const int ra  = wm * 64 + (lane >> 2);
            const int rb  = wn * 32 + (lane >> 2);

            uint32_t af[4][4], bf[4][2];
            #pragma unroll
            for (int mi = 0; mi < 4; mi++) {
                af[mi][0] = Au[(ra + mi * 16    ) * TPITCH + col];
                af[mi][1] = Au[(ra + mi * 16 + 8) * TPITCH + col];
                af[mi][2] = Au[(ra + mi * 16    ) * TPITCH + col + 4];
                af[mi][3] = Au[(ra + mi * 16 + 8) * TPITCH + col + 4];
            }
            #pragma unroll
            for (int ni = 0; ni < 4; ni++) {
                bf[ni][0] = Bu[(rb + ni * 8) * TPITCH + col];
                bf[ni][1] = Bu[(rb + ni * 8) * TPITCH + col + 4];
            }
            #pragma unroll
            for (int mi = 0; mi < 4; mi++)
                #pragma unroll
                for (int ni = 0; ni < 4; ni++)
                    mma_tf32(acc[mi][ni], af[mi][0], af[mi][1], af[mi][2], af[mi][3],
                             bf[ni][0], bf[ni][1]);
        }
        __syncthreads();
    }

    const int lr = lane >> 2;
    const int lc = (lane & 3) * 2;
    #pragma unroll
    for (int mi = 0; mi < 4; mi++) {
        int r0 = bm + wm * 64 + mi * 16 + lr;
        #pragma unroll
        for (int ni = 0; ni < 4; ni++) {
            int c0 = bn + wn * 32 + ni * 8 + lc;
            if (c0 >= N) continue;
            float v0 = acc[mi][ni][0], v1 = acc[mi][ni][1];
            float v2 = acc[mi][ni][2], v3 = acc[mi][ni][3];
            if (bias) {
                float b0 = bias[c0], b1 = bias[c0 + 1];
                v0 += b0; v1 += b1; v2 += b0; v3 += b1;
            }
            if (res) {
                v0 += res[(size_t)r0 * N + c0];
                v1 += res[(size_t)r0 * N + c0 + 1];
                v2 += res[(size_t)(r0 + 8) * N + c0];
                v3 += res[(size_t)(r0 + 8) * N + c0 + 1];
            }
            if (doRelu) {
                v0 = fmaxf(v0, 0.f); v1 = fmaxf(v1, 0.f);
                v2 = fmaxf(v2, 0.f); v3 = fmaxf(v3, 0.f);
            }
            if (outMode) {
                v0 = __uint_as_float(f2tf32(v0));
                v1 = __uint_as_float(f2tf32(v1));
                v2 = __uint_as_float(f2tf32(v2));
                v3 = __uint_as_float(f2tf32(v3));
            }
            *(float2*)&C[(size_t)r0 * N + c0]       = make_float2(v0, v1);
            *(float2*)&C[(size_t)(r0 + 8) * N + c0] = make_float2(v2, v3);
        }
    }
}

// ---------------- tensor-core flash attention --------------------------------
// Q/K/V in fused qkv buffer (stride 1536), tf32 bits, Q pre-scaled.
// Output: tf32 bits (feeds AO gemm as A operand).
#define AP 68
#define FATTN_SMEM ((6 * 64 * AP) * 4)

extern __shared__ float dyn_smem[];

__global__ __launch_bounds__(128) void fattn_tc(
    const float* __restrict__ Q, const float* __restrict__ Kb,
    const float* __restrict__ Vb, float* __restrict__ O)
{
    float* Qs  = dyn_smem;
    float* Ks  = Qs + 64 * AP;
    float* Vk  = Ks + 2 * 64 * AP;
    float* Ss  = Vk + 2 * 64 * AP;

    const int qt = (gridDim.x - 1) - blockIdx.x;
    const int h  = blockIdx.y, b = blockIdx.z;
    const int q0 = qt * 64;
    const int tid  = threadIdx.x;
    const int lane = tid & 31;
    const int warp = tid >> 5;

    const int OST = Hc * DHc;           // 512

    const int r0  = warp * 16 + (lane >> 2);
    const int cq  = lane & 3;
    const int ls4 = lane >> 2;

    #pragma unroll
    for (int p = 0; p < 8; p++) {
        int c = tid + p * 128;
        int r = c >> 4, d4 = (c & 15) * 4;
        float4 v = *(const float4*)(Q + (size_t)(b * Sc + q0 + r) * QKVSTR + h * DHc + d4);
        *(float4*)&Qs[r * AP + d4] = v;
    }

    float o_acc[8][4];
    #pragma unroll
    for (int n = 0; n < 8; n++)
        #pragma unroll
        for (int t = 0; t < 4; t++) o_acc[n][t] = 0.f;
    float m0 = -1e30f, m1 = -1e30f, l0 = 0.f, l1 = 0.f;

    const int nt = qt + 1;
    const size_t kvrow0 = (size_t)(b * Sc) * QKVSTR + h * DHc;

    #pragma unroll
    for (int p = 0; p < 8; p++) {
        int c = tid + p * 128;
        int r = c >> 4, d4 = (c & 15) * 4;
        cp16(&Ks[r * AP + d4], Kb + kvrow0 + (size_t)r * QKVSTR + d4, 16);
        cp16(&Vk[r * AP + d4], Vb + kvrow0 + (size_t)r * QKVSTR + d4, 16);
    }
    asm volatile("cp.async.commit_group;\n");

    for (int kt = 0; kt < nt; kt++) {
        asm volatile("cp.async.wait_group 0;\n");
        __syncthreads();

        const int buf = kt & 1;
        if (kt + 1 < nt) {
            const int nb = buf ^ 1;
            const size_t base = kvrow0 + (size_t)(kt + 1) * 64 * QKVSTR;
            #pragma unroll
            for (int p = 0; p < 8; p++) {
                int c = tid + p * 128;
                int r = c >> 4, d4 = (c & 15) * 4;
                cp16(&Ks[nb * 64 * AP + r * AP + d4], Kb + base + (size_t)r * QKVSTR + d4, 16);
                cp16(&Vk[nb * 64 * AP + r * AP + d4], Vb + base + (size_t)r * QKVSTR + d4, 16);
            }
        }
        asm volatile("cp.async.commit_group;\n");

        const uint32_t* Qu = (const uint32_t*)Qs;
        const uint32_t* Ku = (const uint32_t*)(Ks + buf * 64 * AP);
        const uint32_t* Vu = (const uint32_t*)(Vk + buf * 64 * AP);
        uint32_t*       Pu = (uint32_t*)Ss;

        float sacc[8][4];
        #pragma unroll
        for (int n = 0; n < 8; n++)
            #pragma unroll
            for (int t = 0; t < 4; t++) sacc[n][t] = 0.f;

        #pragma unroll
        for (int k8 = 0; k8 < 8; k8++) {
            const int kcol = k8 * 8 + cq;
            uint32_t a0 = Qu[ r0      * AP + kcol];
            uint32_t a1 = Qu[(r0 + 8) * AP + kcol];
            uint32_t a2 = Qu[ r0      * AP + kcol + 4];
            uint32_t a3 = Qu[(r0 + 8) * AP + kcol + 4];
            #pragma unroll
            for (int n = 0; n < 8; n++) {
                const int nr = n * 8 + ls4;
                mma_tf32(sacc[n], a0, a1, a2, a3,
                         Ku[nr * AP + kcol], Ku[nr * AP + kcol + 4]);
            }
        }

        if (kt == qt) {
            #pragma unroll
            for (int n = 0; n < 8; n++) {
                const int c0 = n * 8 + cq * 2;
                if (c0     > r0)     sacc[n][0] = -1e30f;
                if (c0 + 1 > r0)     sacc[n][1] = -1e30f;
                if (c0     > r0 + 8) sacc[n][2] = -1e30f;
                if (c0 + 1 > r0 + 8) sacc[n][3] = -1e30f;
            }
        }

        float mx0 = -1e30f, mx1 = -1e30f;
        #pragma unroll
        for (int n = 0; n < 8; n++) {
            mx0 = fmaxf(mx0, fmaxf(sacc[n][0], sacc[n][1]));
            mx1 = fmaxf(mx1, fmaxf(sacc[n][2], sacc[n][3]));
        }
        mx0 = fmaxf(mx0, __shfl_xor_sync(0xffffffffu, mx0, 1));
        mx0 = fmaxf(mx0, __shfl_xor_sync(0xffffffffu, mx0, 2));
        mx1 = fmaxf(mx1, __shfl_xor_sync(0xffffffffu, mx1, 1));
        mx1 = fmaxf(mx1, __shfl_xor_sync(0xffffffffu, mx1, 2));

        const float mn0 = fmaxf(m0, mx0);
        const float mn1 = fmaxf(m1, mx1);
        const float cr0 = __expf(m0 - mn0);
        const float cr1 = __expf(m1 - mn1);
        float s0 = 0.f, s1 = 0.f;
        #pragma unroll
        for (int n = 0; n < 8; n++) {
            float p00 = __expf(sacc[n][0] - mn0);
            float p01 = __expf(sacc[n][1] - mn0);
            float p10 = __expf(sacc[n][2] - mn1);
            float p11 = __expf(sacc[n][3] - mn1);
            s0 += p00 + p01;
            s1 += p10 + p11;
            const int c0 = n * 8 + cq * 2;
            *(uint2*)&Pu[ r0      * AP + c0] = make_uint2(f2tf32(p00), f2tf32(p01));
            *(uint2*)&Pu[(r0 + 8) * AP + c0] = make_uint2(f2tf32(p10), f2tf32(p11));
        }
        s0 += __shfl_xor_sync(0xffffffffu, s0, 1);
        s0 += __shfl_xor_sync(0xffffffffu, s0, 2);
        s1 += __shfl_xor_sync(0xffffffffu, s1, 1);
        s1 += __shfl_xor_sync(0xffffffffu, s1, 2);

        l0 = l0 * cr0 + s0;  m0 = mn0;
        l1 = l1 * cr1 + s1;  m1 = mn1;
        #pragma unroll
        for (int n = 0; n < 8; n++) {
            o_acc[n][0] *= cr0; o_acc[n][1] *= cr0;
            o_acc[n][2] *= cr1; o_acc[n][3] *= cr1;
        }
        __syncwarp();

        #pragma unroll
        for (int k8 = 0; k8 < 8; k8++) {
            const int kcol = k8 * 8 + cq;
            uint32_t a0 = Pu[ r0      * AP + kcol];
            uint32_t a1 = Pu[(r0 + 8) * AP + kcol];
            uint32_t a2 = Pu[ r0      * AP + kcol + 4];
            uint32_t a3 = Pu[(r0 + 8) * AP + kcol + 4];
            #pragma unroll
            for (int n = 0; n < 8; n++) {
                const int nr = n * 8 + ls4;
                mma_tf32(o_acc[n], a0, a1, a2, a3,
                         Vu[kcol * AP + nr], Vu[(kcol + 4) * AP + nr]);
            }
        }
    }

    // epilogue: tf32 bits, coalesced float2 stores
    const float inv0 = 1.f / l0;
    const float inv1 = 1.f / l1;
    #pragma unroll
    for (int n = 0; n < 8; n++) {
        const int c0 = n * 8 + cq * 2;
        size_t o0 = (size_t)(b * Sc + q0 + r0)     * OST + h * DHc + c0;
        size_t o1 = (size_t)(b * Sc + q0 + r0 + 8) * OST + h * DHc + c0;
        *(float2*)&O[o0] = make_float2(__uint_as_float(f2tf32(o_acc[n][0] * inv0)),
                                       __uint_as_float(f2tf32(o_acc[n][1] * inv0)));
        *(float2*)&O[o1] = make_float2(__uint_as_float(f2tf32(o_acc[n][2] * inv1)),
                                       __uint_as_float(f2tf32(o_acc[n][3] * inv1)));
    }
}

// ---------------- LayerNorm over D=512 (dual output: fp32 + tf32 bits) -------
__global__ void ln_kernel(const float* __restrict__ X, const float* __restrict__ g,
                          const float* __restrict__ bta, float* __restrict__ Y,
                          float* __restrict__ Yt) {
    int row = blockIdx.x;
    const float* x = X + (size_t)row * Dc;
    float* y  = Y  + (size_t)row * Dc;
    float* yt = Yt + (size_t)row * Dc;
    int tid = threadIdx.x;

    float v[4];
    float sum = 0.f;
    #pragma unroll
    for (int i = 0; i < 4; i++) { v[i] = x[tid + i*128]; sum += v[i]; }

    __shared__ float red[4];
    #pragma unroll
    for (int off = 16; off; off >>= 1) sum += __shfl_xor_sync(0xffffffffu, sum, off);
    if ((tid & 31) == 0) red[tid >> 5] = sum;
    __syncthreads();
    sum = red[0] + red[1] + red[2] + red[3];
    float mean = sum * (1.f / Dc);

    float sq = 0.f;
    #pragma unroll
    for (int i = 0; i < 4; i++) { float d = v[i] - mean; sq += d * d; }
    __shared__ float red2[4];
    #pragma unroll
    for (int off = 16; off; off >>= 1) sq += __shfl_xor_sync(0xffffffffu, sq, off);
    if ((tid & 31) == 0) red2[tid >> 5] = sq;
    __syncthreads();
    sq = red2[0] + red2[1] + red2[2] + red2[3];
    float rstd = rsqrtf(sq * (1.f / Dc) + 1e-5f);

    #pragma unroll
    for (int i = 0; i < 4; i++) {
        int d = tid + i*128;
        float o = (v[i] - mean) * rstd * g[d] + bta[d];
        y[d]  = o;
        yt[d] = __uint_as_float(f2tf32(o));
    }
}

// ---------------- launch ----------------------------------------------------
extern "C" void kernel_launch(void* const* d_in, const int* in_sizes, int n_in,
                              void* d_out, int out_size) {
    const int*   data = (const int*)  d_in[0];
    const float* we   = (const float*)d_in[1];
    const float* pe   = (const float*)d_in[2];
    const float* Wq   = (const float*)d_in[3];
    const float* Wkv  = (const float*)d_in[4];
    const float* Wo   = (const float*)d_in[5];
    const float* g1   = (const float*)d_in[6];
    const float* bl1  = (const float*)d_in[7];
    const float* W1   = (const float*)d_in[8];
    const float* bf1  = (const float*)d_in[9];
    const float* W2   = (const float*)d_in[10];
    const float* bf2  = (const float*)d_in[11];
    const float* g2   = (const float*)d_in[12];
    const float* bl2  = (const float*)d_in[13];
    const float* outb = (const float*)d_in[14];
    float* out = (float*)d_out;

    float *h, *ht, *qkv, *aot, *tmp, *fft;
    float *wqkv, *wo_t, *w1_t, *w2_t, *we_t;
    cudaGetSymbolAddress((void**)&h,    g_h);
    cudaGetSymbolAddress((void**)&ht,   g_ht);
    cudaGetSymbolAddress((void**)&qkv,  g_qkv);
    cudaGetSymbolAddress((void**)&aot,  g_aot);
    cudaGetSymbolAddress((void**)&tmp,  g_tmp);
    cudaGetSymbolAddress((void**)&fft,  g_fft);
    cudaGetSymbolAddress((void**)&wqkv, g_wqkv);
    cudaGetSymbolAddress((void**)&wo_t, g_wo_t);
    cudaGetSymbolAddress((void**)&w1_t, g_w1_t);
    cudaGetSymbolAddress((void**)&w2_t, g_w2_t);
    cudaGetSymbolAddress((void**)&we_t, g_we_t);

    cudaFuncSetAttribute(fattn_tc, cudaFuncAttributeMaxDynamicSharedMemorySize, FATTN_SMEM);

    // weight preconversion (tf32 bits)
    {
        int n;
        n = Lc * QKVSTR * Dc;  pack_qkv_w<<<(n + 255)/256, 256>>>(Wq, Wkv, wqkv);
        n = Lc * Dc * Dc;      cvt_w<<<(n + 255)/256, 256>>>(Wo, wo_t, n);
        n = Lc * DIc * Dc;     cvt_w<<<(n + 255)/256, 256>>>(W1, w1_t, n);
        n = Lc * Dc * DIc;     cvt_w<<<(n + 255)/256, 256>>>(W2, w2_t, n);
        n = Vc * Dc;           cvt_w<<<(n + 255)/256, 256>>>(we, we_t, n);
    }

    embed_kernel<<<(M_ROWS*Dc + 255)/256, 256>>>(data, we, pe, h, ht);

    dim3 gsD  (( Dc     + 127)/128, M_ROWS/128);
    dim3 gsQKV((QKVSTR  + 127)/128, M_ROWS/128);
    dim3 gsDI (( DIc    + 127)/128, M_ROWS/128);
    dim3 gsV  (( Vc     + 127)/128, M_ROWS/128);
    dim3 gsA  (Sc/64, Hc, Bc);

    for (int l = 0; l < Lc; l++) {
        tgemm_kernel<<<gsQKV, 256>>>(ht, wqkv + (size_t)l*QKVSTR*Dc, nullptr, nullptr,
                                     qkv, M_ROWS, QKVSTR, Dc, 0, 1);

        fattn_tc<<<gsA, 128, FATTN_SMEM>>>(qkv, qkv + Dc, qkv + 2*Dc, aot);

        tgemm_kernel<<<gsD, 256>>>(aot, wo_t + (size_t)l*Dc*Dc, nullptr, h, tmp,
                                   M_ROWS, Dc, Dc, 0, 0);
        ln_kernel<<<M_ROWS, 128>>>(tmp, g1 + (size_t)l*Dc, bl1 + (size_t)l*Dc, h, ht);

        tgemm_kernel<<<gsDI, 256>>>(ht, w1_t + (size_t)l*DIc*Dc, bf1 + (size_t)l*DIc, nullptr,
                                    fft, M_ROWS, DIc, Dc, 1, 1);
        tgemm_kernel<<<gsD, 256>>>(fft, w2_t + (size_t)l*Dc*DIc, bf2 + (size_t)l*Dc, h,
                                   tmp, M_ROWS, Dc, DIc, 0, 0);
        ln_kernel<<<M_ROWS, 128>>>(tmp, g2 + (size_t)l*Dc, bl2 + (size_t)l*Dc, h, ht);
    }

    tgemm_kernel<<<gsV, 256>>>(ht, we_t, outb, nullptr, out, M_ROWS, Vc, Dc, 0, 0);
}

// round 8
// speedup vs baseline: 1.5833x; 1.4546x over previous
#include <cuda_runtime.h>
#include <cuda_fp16.h>
#include <math.h>
#include <stdint.h>

#define Bc 4
#define Sc 1024
#define Dc 512
#define Hc 8
#define DHc 64
#define DIc 2048
#define Lc 12
#define Vc 10000
#define M_ROWS (Bc*Sc)   /* 4096 */
#define QKVSTR (3*Dc)    /* 1536 */

// ---------------- scratch (no allocations allowed) ----------------
__device__ float  g_h   [M_ROWS*Dc];      // fp32 residual stream
__device__ __half g_ht  [M_ROWS*Dc];      // fp16 (GEMM A operand)
__device__ __half g_qkv [M_ROWS*QKVSTR];  // fp16 attn operands (Q pre-scaled)
__device__ __half g_aot [M_ROWS*Dc];      // fp16 attn out
__device__ float  g_tmp [M_ROWS*Dc];
__device__ __half g_fft [M_ROWS*DIc];     // fp16 FF1 out
// fp16 preconverted weights
__device__ __half g_wqkv[Lc*QKVSTR*Dc];
__device__ __half g_wo_t[Lc*Dc*Dc];
__device__ __half g_w1_t[Lc*DIc*Dc];
__device__ __half g_w2_t[Lc*Dc*DIc];
__device__ __half g_we_t[Vc*Dc];

// ---------------- helpers ----------------------------------------------------
__device__ __forceinline__ void cp16(void* smem, const void* g, int srcBytes) {
    uint32_t s = (uint32_t)__cvta_generic_to_shared(smem);
    asm volatile("cp.async.cg.shared.global [%0], [%1], 16, %2;\n"
                 :: "r"(s), "l"(g), "r"(srcBytes));
}

// fp16 mma: D(16x8,f32) += A(16x16,f16) * B(8x16,f16)^T
__device__ __forceinline__ void mma_f16(float c[4],
    uint32_t a0, uint32_t a1, uint32_t a2, uint32_t a3,
    uint32_t b0, uint32_t b1)
{
    asm volatile(
        "mma.sync.aligned.m16n8k16.row.col.f32.f16.f16.f32 "
        "{%0,%1,%2,%3}, {%4,%5,%6,%7}, {%8,%9}, {%0,%1,%2,%3};"
        : "+f"(c[0]), "+f"(c[1]), "+f"(c[2]), "+f"(c[3])
        : "r"(a0), "r"(a1), "r"(a2), "r"(a3), "r"(b0), "r"(b1));
}

__device__ __forceinline__ void ldsm_x2_trans(uint32_t& r0, uint32_t& r1, uint32_t addr) {
    asm volatile("ldmatrix.sync.aligned.m8n8.x2.trans.shared.b16 {%0,%1}, [%2];"
                 : "=r"(r0), "=r"(r1) : "r"(addr));
}

// ---------------- weight preconversion (fp16) --------------------------------
__global__ void pack_qkv_w(const float* __restrict__ Wq, const float* __restrict__ Wkv,
                           __half* __restrict__ dst) {
    int i = blockIdx.x * blockDim.x + threadIdx.x;
    if (i >= Lc * QKVSTR * Dc) return;
    int c = i % Dc;
    int r = (i / Dc) % QKVSTR;
    int l = i / (Dc * QKVSTR);
    float v;
    if (r < Dc) v = Wq[((size_t)l * Dc + r) * Dc + c] * 0.125f;
    else        v = Wkv[((size_t)l * 2 * Dc + (r - Dc)) * Dc + c];
    dst[i] = __float2half_rn(v);
}

__global__ void cvt_w(const float* __restrict__ src, __half* __restrict__ dst, int n) {
    int i = blockIdx.x * blockDim.x + threadIdx.x;
    if (i < n) dst[i] = __float2half_rn(src[i]);
}

// ---------------- embedding ----------------
__global__ void embed_kernel(const int* __restrict__ data,
                             const float* __restrict__ we,
                             const float* __restrict__ pe,
                             float* __restrict__ h, __half* __restrict__ ht) {
    int i = blockIdx.x * blockDim.x + threadIdx.x;
    if (i >= M_ROWS * Dc) return;
    int d   = i % Dc;
    int row = i / Dc;
    int s   = row % Sc;
    int tok = data[row];
    float v = we[(size_t)tok * Dc + d] + pe[(size_t)s * Dc + d];
    h[i]  = v;
    ht[i] = __float2half_rn(v);
}

// ---------------- fp16 tensor-core GEMM --------------------------------------
// C[M,N] = A[M,K] @ W[N,K]^T. A,W fp16. outMode: 0 = fp32 out, 1 = fp16 out
#define TBM 128
#define TBN 128
#define TBK 16
#define TP 24   // halves: 48B pitch -> banks 12r+(lane&3), conflict-free

__global__ __launch_bounds__(256) void tgemm_kernel(
    const __half* __restrict__ A, const __half* __restrict__ W,
    const float* __restrict__ bias, const float* __restrict__ res,
    void* __restrict__ Cv, int M, int N, int K, int doRelu, int outMode)
{
    __shared__ __align__(16) __half As[2][TBM][TP];
    __shared__ __align__(16) __half Bs[2][TBN][TP];

    const int tid  = threadIdx.x;
    const int lane = tid & 31;
    const int warp = tid >> 5;
    const int wm   = warp >> 2;
    const int wn   = warp & 3;
    const int bm   = blockIdx.y * TBM;
    const int bn   = blockIdx.x * TBN;

    // loaders: 128 rows x 32B/row per tile; thread t: row=t>>1, 16B chunk (t&1)
    const int lrow = tid >> 1;
    const int lo8  = (tid & 1) * 8;     // half offset

    float acc[4][4][4];
    #pragma unroll
    for (int i = 0; i < 4; i++)
        #pragma unroll
        for (int j = 0; j < 4; j++)
            #pragma unroll
            for (int t = 0; t < 4; t++) acc[i][j][t] = 0.f;

    const int KT = K / TBK;

    {
        cp16(&As[0][lrow][lo8], A + (size_t)(bm + lrow) * K + lo8, 16);
        int gn = bn + lrow;
        int ok = (gn < N) ? 16 : 0;
        int gc = (gn < N) ? gn : (N - 1);
        cp16(&Bs[0][lrow][lo8], W + (size_t)gc * K + lo8, ok);
        asm volatile("cp.async.commit_group;\n");
    }

    for (int t = 0; t < KT; t++) {
        asm volatile("cp.async.wait_group 0;\n");
        __syncthreads();

        if (t + 1 < KT) {
            int nb = (t + 1) & 1;
            int k0 = (t + 1) * TBK;
            cp16(&As[nb][lrow][lo8], A + (size_t)(bm + lrow) * K + k0 + lo8, 16);
            int gn = bn + lrow;
            int ok = (gn < N) ? 16 : 0;
            int gc = (gn < N) ? gn : (N - 1);
            cp16(&Bs[nb][lrow][lo8], W + (size_t)gc * K + k0 + lo8, ok);
            asm volatile("cp.async.commit_group;\n");
        }

        const int buf = t & 1;
        const int kh  = (lane & 3) * 2;          // half col within k16
        const int ra  = wm * 64 + (lane >> 2);
        const int rb  = wn * 32 + (lane >> 2);

        uint32_t af[4][4], bf[4][2];
        #pragma unroll
        for (int mi = 0; mi < 4; mi++) {
            af[mi][0] = *(const uint32_t*)&As[buf][ra + mi * 16    ][kh];
            af[mi][1] = *(const uint32_t*)&As[buf][ra + mi * 16 + 8][kh];
            af[mi][2] = *(const uint32_t*)&As[buf][ra + mi * 16    ][kh + 8];
            af[mi][3] = *(const uint32_t*)&As[buf][ra + mi * 16 + 8][kh + 8];
        }
        #pragma unroll
        for (int ni = 0; ni < 4; ni++) {
            bf[ni][0] = *(const uint32_t*)&Bs[buf][rb + ni * 8][kh];
            bf[ni][1] = *(const uint32_t*)&Bs[buf][rb + ni * 8][kh + 8];
        }
        #pragma unroll
        for (int mi = 0; mi < 4; mi++)
            #pragma unroll
            for (int ni = 0; ni < 4; ni++)
                mma_f16(acc[mi][ni], af[mi][0], af[mi][1], af[mi][2], af[mi][3],
                        bf[ni][0], bf[ni][1]);
        __syncthreads();
    }

    const int lr = lane >> 2;
    const int lc = (lane & 3) * 2;
    #pragma unroll
    for (int mi = 0; mi < 4; mi++) {
        int r0 = bm + wm * 64 + mi * 16 + lr;
        #pragma unroll
        for (int ni = 0; ni < 4; ni++) {
            int c0 = bn + wn * 32 + ni * 8 + lc;
            if (c0 >= N) continue;
            float v0 = acc[mi][ni][0], v1 = acc[mi][ni][1];
            float v2 = acc[mi][ni][2], v3 = acc[mi][ni][3];
            if (bias) {
                float b0 = bias[c0], b1 = bias[c0 + 1];
                v0 += b0; v1 += b1; v2 += b0; v3 += b1;
            }
            if (res) {
                v0 += res[(size_t)r0 * N + c0];
                v1 += res[(size_t)r0 * N + c0 + 1];
                v2 += res[(size_t)(r0 + 8) * N + c0];
                v3 += res[(size_t)(r0 + 8) * N + c0 + 1];
            }
            if (doRelu) {
                v0 = fmaxf(v0, 0.f); v1 = fmaxf(v1, 0.f);
                v2 = fmaxf(v2, 0.f); v3 = fmaxf(v3, 0.f);
            }
            if (outMode == 0) {
                float* C = (float*)Cv;
                *(float2*)&C[(size_t)r0 * N + c0]       = make_float2(v0, v1);
                *(float2*)&C[(size_t)(r0 + 8) * N + c0] = make_float2(v2, v3);
            } else {
                __half* C = (__half*)Cv;
                *(__half2*)&C[(size_t)r0 * N + c0]       = __floats2half2_rn(v0, v1);
                *(__half2*)&C[(size_t)(r0 + 8) * N + c0] = __floats2half2_rn(v2, v3);
            }
        }
    }
}

// ---------------- fp16 tensor-core flash attention ---------------------------
// 64q x 64k tiles, 4 warps. Q/K/V fp16 in fused qkv buffer (stride 1536 halves).
// V B-fragments via ldmatrix.x2.trans. Output: fp16.
#define APH 72   // halves: 144B pitch -> banks 36r mod 32 = 4r, conflict-free
#define FATTN_SMEM (6 * 64 * APH * 2)

extern __shared__ __half attn_smem[];

__global__ __launch_bounds__(128) void fattn_tc(
    const __half* __restrict__ Q, const __half* __restrict__ Kb,
    const __half* __restrict__ Vb, __half* __restrict__ O)
{
    __half* Qs = attn_smem;               // [64][APH]
    __half* Ks = Qs + 64 * APH;           // 2 x [64][APH]
    __half* Vk = Ks + 2 * 64 * APH;       // 2 x [64][APH]  (row k, col d)
    __half* Ps = Vk + 2 * 64 * APH;       // [64][APH]

    const int qt = (gridDim.x - 1) - blockIdx.x;
    const int h  = blockIdx.y, b = blockIdx.z;
    const int q0 = qt * 64;
    const int tid  = threadIdx.x;
    const int lane = tid & 31;
    const int warp = tid >> 5;

    const int OST = Hc * DHc;             // 512

    const int r0  = warp * 16 + (lane >> 2);
    const int kh  = (lane & 3) * 2;       // half col in k16
    const int ls4 = lane >> 2;

    // load Q tile: 64 rows x 128B; 512 chunks of 16B over 128 threads
    #pragma unroll
    for (int p = 0; p < 4; p++) {
        int c = tid + p * 128;
        int r = c >> 3, d8 = (c & 7) * 8;
        float4 v = *(const float4*)(Q + (size_t)(b * Sc + q0 + r) * QKVSTR + h * DHc + d8);
        *(float4*)&Qs[r * APH + d8] = v;
    }

    float o_acc[8][4];
    #pragma unroll
    for (int n = 0; n < 8; n++)
        #pragma unroll
        for (int t = 0; t < 4; t++) o_acc[n][t] = 0.f;
    float m0 = -1e30f, m1 = -1e30f, l0 = 0.f, l1 = 0.f;

    const int nt = qt + 1;
    const size_t kvrow0 = (size_t)(b * Sc) * QKVSTR + h * DHc;

    #pragma unroll
    for (int p = 0; p < 4; p++) {
        int c = tid + p * 128;
        int r = c >> 3, d8 = (c & 7) * 8;
        cp16(&Ks[r * APH + d8], Kb + kvrow0 + (size_t)r * QKVSTR + d8, 16);
        cp16(&Vk[r * APH + d8], Vb + kvrow0 + (size_t)r * QKVSTR + d8, 16);
    }
    asm volatile("cp.async.commit_group;\n");

    for (int kt = 0; kt < nt; kt++) {
        asm volatile("cp.async.wait_group 0;\n");
        __syncthreads();

        const int buf = kt & 1;
        if (kt + 1 < nt) {
            const int nb = buf ^ 1;
            const size_t base = kvrow0 + (size_t)(kt + 1) * 64 * QKVSTR;
            #pragma unroll
            for (int p = 0; p < 4; p++) {
                int c = tid + p * 128;
                int r = c >> 3, d8 = (c & 7) * 8;
                cp16(&Ks[nb * 64 * APH + r * APH + d8], Kb + base + (size_t)r * QKVSTR + d8, 16);
                cp16(&Vk[nb * 64 * APH + r * APH + d8], Vb + base + (size_t)r * QKVSTR + d8, 16);
            }
        }
        asm volatile("cp.async.commit_group;\n");

        const __half* Kt = Ks + buf * 64 * APH;
        const __half* Vt = Vk + buf * 64 * APH;

        // S = Q @ K^T : 4 k16 steps over DH=64
        float sacc[8][4];
        #pragma unroll
        for (int n = 0; n < 8; n++)
            #pragma unroll
            for (int t = 0; t < 4; t++) sacc[n][t] = 0.f;

        #pragma unroll
        for (int ks = 0; ks < 4; ks++) {
            const int kb = ks * 16;
            uint32_t a0 = *(const uint32_t*)&Qs[ r0      * APH + kb + kh];
            uint32_t a1 = *(const uint32_t*)&Qs[(r0 + 8) * APH + kb + kh];
            uint32_t a2 = *(const uint32_t*)&Qs[ r0      * APH + kb + kh + 8];
            uint32_t a3 = *(const uint32_t*)&Qs[(r0 + 8) * APH + kb + kh + 8];
            #pragma unroll
            for (int n = 0; n < 8; n++) {
                const int nr = n * 8 + ls4;
                uint32_t b0 = *(const uint32_t*)&Kt[nr * APH + kb + kh];
                uint32_t b1 = *(const uint32_t*)&Kt[nr * APH + kb + kh + 8];
                mma_f16(sacc[n], a0, a1, a2, a3, b0, b1);
            }
        }

        if (kt == qt) {
            #pragma unroll
            for (int n = 0; n < 8; n++) {
                const int c0 = n * 8 + (lane & 3) * 2;
                if (c0     > r0)     sacc[n][0] = -1e30f;
                if (c0 + 1 > r0)     sacc[n][1] = -1e30f;
                if (c0     > r0 + 8) sacc[n][2] = -1e30f;
                if (c0 + 1 > r0 + 8) sacc[n][3] = -1e30f;
            }
        }

        // online softmax (rows warp-local; quad reduce)
        float mx0 = -1e30f, mx1 = -1e30f;
        #pragma unroll
        for (int n = 0; n < 8; n++) {
            mx0 = fmaxf(mx0, fmaxf(sacc[n][0], sacc[n][1]));
            mx1 = fmaxf(mx1, fmaxf(sacc[n][2], sacc[n][3]));
        }
        mx0 = fmaxf(mx0, __shfl_xor_sync(0xffffffffu, mx0, 1));
        mx0 = fmaxf(mx0, __shfl_xor_sync(0xffffffffu, mx0, 2));
        mx1 = fmaxf(mx1, __shfl_xor_sync(0xffffffffu, mx1, 1));
        mx1 = fmaxf(mx1, __shfl_xor_sync(0xffffffffu, mx1, 2));

        const float mn0 = fmaxf(m0, mx0);
        const float mn1 = fmaxf(m1, mx1);
        const float cr0 = __expf(m0 - mn0);
        const float cr1 = __expf(m1 - mn1);
        float s0 = 0.f, s1 = 0.f;
        #pragma unroll
        for (int n = 0; n < 8; n++) {
            float p00 = __expf(sacc[n][0] - mn0);
            float p01 = __expf(sacc[n][1] - mn0);
            float p10 = __expf(sacc[n][2] - mn1);
            float p11 = __expf(sacc[n][3] - mn1);
            s0 += p00 + p01;
            s1 += p10 + p11;
            const int c0 = n * 8 + (lane & 3) * 2;
            *(__half2*)&Ps[ r0      * APH + c0] = __floats2half2_rn(p00, p01);
            *(__half2*)&Ps[(r0 + 8) * APH + c0] = __floats2half2_rn(p10, p11);
        }
        s0 += __shfl_xor_sync(0xffffffffu, s0, 1);
        s0 += __shfl_xor_sync(0xffffffffu, s0, 2);
        s1 += __shfl_xor_sync(0xffffffffu, s1, 1);
        s1 += __shfl_xor_sync(0xffffffffu, s1, 2);

        l0 = l0 * cr0 + s0;  m0 = mn0;
        l1 = l1 * cr1 + s1;  m1 = mn1;
        #pragma unroll
        for (int n = 0; n < 8; n++) {
            o_acc[n][0] *= cr0; o_acc[n][1] *= cr0;
            o_acc[n][2] *= cr1; o_acc[n][3] *= cr1;
        }
        __syncwarp();

        // O += P @ V : B fragments via ldmatrix.x2.trans from Vt[k][d]
        #pragma unroll
        for (int ks = 0; ks < 4; ks++) {
            const int kb = ks * 16;
            uint32_t a0 = *(const uint32_t*)&Ps[ r0      * APH + kb + kh];
            uint32_t a1 = *(const uint32_t*)&Ps[(r0 + 8) * APH + kb + kh];
            uint32_t a2 = *(const uint32_t*)&Ps[ r0      * APH + kb + kh + 8];
            uint32_t a3 = *(const uint32_t*)&Ps[(r0 + 8) * APH + kb + kh + 8];
            // lane's ldmatrix row address: rows kb..kb+15 (lanes 0-15), 16B segments
            uint32_t base = (uint32_t)__cvta_generic_to_shared(
                                &Vt[(kb + (lane & 15)) * APH]);
            #pragma unroll
            for (int n = 0; n < 8; n++) {
                uint32_t b0, b1;
                ldsm_x2_trans(b0, b1, base + n * 16);
                mma_f16(o_acc[n], a0, a1, a2, a3, b0, b1);
            }
        }
    }

    const float inv0 = 1.f / l0;
    const float inv1 = 1.f / l1;
    #pragma unroll
    for (int n = 0; n < 8; n++) {
        const int c0 = n * 8 + (lane & 3) * 2;
        size_t o0 = (size_t)(b * Sc + q0 + r0)     * OST + h * DHc + c0;
        size_t o1 = (size_t)(b * Sc + q0 + r0 + 8) * OST + h * DHc + c0;
        *(__half2*)&O[o0] = __floats2half2_rn(o_acc[n][0] * inv0, o_acc[n][1] * inv0);
        *(__half2*)&O[o1] = __floats2half2_rn(o_acc[n][2] * inv1, o_acc[n][3] * inv1);
    }
}

// ---------------- LayerNorm over D=512 (dual output: fp32 + fp16) ------------
__global__ void ln_kernel(const float* __restrict__ X, const float* __restrict__ g,
                          const float* __restrict__ bta, float* __restrict__ Y,
                          __half* __restrict__ Yt) {
    int row = blockIdx.x;
    const float* x = X + (size_t)row * Dc;
    float*  y  = Y  + (size_t)row * Dc;
    __half* yt = Yt + (size_t)row * Dc;
    int tid = threadIdx.x;

    float v[4];
    float sum = 0.f;
    #pragma unroll
    for (int i = 0; i < 4; i++) { v[i] = x[tid + i*128]; sum += v[i]; }

    __shared__ float red[4];
    #pragma unroll
    for (int off = 16; off; off >>= 1) sum += __shfl_xor_sync(0xffffffffu, sum, off);
    if ((tid & 31) == 0) red[tid >> 5] = sum;
    __syncthreads();
    sum = red[0] + red[1] + red[2] + red[3];
    float mean = sum * (1.f / Dc);

    float sq = 0.f;
    #pragma unroll
    for (int i = 0; i < 4; i++) { float d = v[i] - mean; sq += d * d; }
    __shared__ float red2[4];
    #pragma unroll
    for (int off = 16; off; off >>= 1) sq += __shfl_xor_sync(0xffffffffu, sq, off);
    if ((tid & 31) == 0) red2[tid >> 5] = sq;
    __syncthreads();
    sq = red2[0] + red2[1] + red2[2] + red2[3];
    float rstd = rsqrtf(sq * (1.f / Dc) + 1e-5f);

    #pragma unroll
    for (int i = 0; i < 4; i++) {
        int d = tid + i*128;
        float o = (v[i] - mean) * rstd * g[d] + bta[d];
        y[d]  = o;
        yt[d] = __float2half_rn(o);
    }
}

// ---------------- launch ----------------------------------------------------
extern "C" void kernel_launch(void* const* d_in, const int* in_sizes, int n_in,
                              void* d_out, int out_size) {
    const int*   data = (const int*)  d_in[0];
    const float* we   = (const float*)d_in[1];
    const float* pe   = (const float*)d_in[2];
    const float* Wq   = (const float*)d_in[3];
    const float* Wkv  = (const float*)d_in[4];
    const float* Wo   = (const float*)d_in[5];
    const float* g1   = (const float*)d_in[6];
    const float* bl1  = (const float*)d_in[7];
    const float* W1   = (const float*)d_in[8];
    const float* bf1  = (const float*)d_in[9];
    const float* W2   = (const float*)d_in[10];
    const float* bf2  = (const float*)d_in[11];
    const float* g2   = (const float*)d_in[12];
    const float* bl2  = (const float*)d_in[13];
    const float* outb = (const float*)d_in[14];
    float* out = (float*)d_out;

    float *h, *tmp;
    __half *ht, *qkv, *aot, *fft;
    __half *wqkv, *wo_t, *w1_t, *w2_t, *we_t;
    cudaGetSymbolAddress((void**)&h,    g_h);
    cudaGetSymbolAddress((void**)&ht,   g_ht);
    cudaGetSymbolAddress((void**)&qkv,  g_qkv);
    cudaGetSymbolAddress((void**)&aot,  g_aot);
    cudaGetSymbolAddress((void**)&tmp,  g_tmp);
    cudaGetSymbolAddress((void**)&fft,  g_fft);
    cudaGetSymbolAddress((void**)&wqkv, g_wqkv);
    cudaGetSymbolAddress((void**)&wo_t, g_wo_t);
    cudaGetSymbolAddress((void**)&w1_t, g_w1_t);
    cudaGetSymbolAddress((void**)&w2_t, g_w2_t);
    cudaGetSymbolAddress((void**)&we_t, g_we_t);

    cudaFuncSetAttribute(fattn_tc, cudaFuncAttributeMaxDynamicSharedMemorySize, FATTN_SMEM);

    // weight preconversion (fp16)
    {
        int n;
        n = Lc * QKVSTR * Dc;  pack_qkv_w<<<(n + 255)/256, 256>>>(Wq, Wkv, wqkv);
        n = Lc * Dc * Dc;      cvt_w<<<(n + 255)/256, 256>>>(Wo, wo_t, n);
        n = Lc * DIc * Dc;     cvt_w<<<(n + 255)/256, 256>>>(W1, w1_t, n);
        n = Lc * Dc * DIc;     cvt_w<<<(n + 255)/256, 256>>>(W2, w2_t, n);
        n = Vc * Dc;           cvt_w<<<(n + 255)/256, 256>>>(we, we_t, n);
    }

    embed_kernel<<<(M_ROWS*Dc + 255)/256, 256>>>(data, we, pe, h, ht);

    dim3 gsD  (( Dc     + 127)/128, M_ROWS/128);
    dim3 gsQKV((QKVSTR  + 127)/128, M_ROWS/128);
    dim3 gsDI (( DIc    + 127)/128, M_ROWS/128);
    dim3 gsV  (( Vc     + 127)/128, M_ROWS/128);
    dim3 gsA  (Sc/64, Hc, Bc);

    for (int l = 0; l < Lc; l++) {
        tgemm_kernel<<<gsQKV, 256>>>(ht, wqkv + (size_t)l*QKVSTR*Dc, nullptr, nullptr,
                                     qkv, M_ROWS, QKVSTR, Dc, 0, 1);

        fattn_tc<<<gsA, 128, FATTN_SMEM>>>(qkv, qkv + Dc, qkv + 2*Dc, aot);

        tgemm_kernel<<<gsD, 256>>>(aot, wo_t + (size_t)l*Dc*Dc, nullptr, h, tmp,
                                   M_ROWS, Dc, Dc, 0, 0);
        ln_kernel<<<M_ROWS, 128>>>(tmp, g1 + (size_t)l*Dc, bl1 + (size_t)l*Dc, h, ht);

        tgemm_kernel<<<gsDI, 256>>>(ht, w1_t + (size_t)l*DIc*Dc, bf1 + (size_t)l*DIc, nullptr,
                                    fft, M_ROWS, DIc, Dc, 1, 1);
        tgemm_kernel<<<gsD, 256>>>(fft, w2_t + (size_t)l*Dc*DIc, bf2 + (size_t)l*Dc, h,
                                   tmp, M_ROWS, Dc, DIc, 0, 0);
        ln_kernel<<<M_ROWS, 128>>>(tmp, g2 + (size_t)l*Dc, bl2 + (size_t)l*Dc, h, ht);
    }

    tgemm_kernel<<<gsV, 256>>>(ht, we_t, outb, nullptr, out, M_ROWS, Vc, Dc, 0, 0);
}

// round 9
// speedup vs baseline: 2.0488x; 1.2940x over previous
#include <cuda_runtime.h>
#include <cuda_fp16.h>
#include <math.h>
#include <stdint.h>

#define Bc 4
#define Sc 1024
#define Dc 512
#define Hc 8
#define DHc 64
#define DIc 2048
#define Lc 12
#define Vc 10000
#define M_ROWS (Bc*Sc)   /* 4096 */
#define QKVSTR (3*Dc)    /* 1536 */

// ---------------- scratch (no allocations allowed) ----------------
__device__ float  g_h   [M_ROWS*Dc];
__device__ __half g_ht  [M_ROWS*Dc];
__device__ __half g_qkv [M_ROWS*QKVSTR];
__device__ __half g_aot [M_ROWS*Dc];
__device__ float  g_tmp [M_ROWS*Dc];
__device__ __half g_fft [M_ROWS*DIc];
__device__ __half g_wqkv[Lc*QKVSTR*Dc];
__device__ __half g_wo_t[Lc*Dc*Dc];
__device__ __half g_w1_t[Lc*DIc*Dc];
__device__ __half g_w2_t[Lc*Dc*DIc];
__device__ __half g_we_t[Vc*Dc];

// ---------------- helpers ----------------------------------------------------
__device__ __forceinline__ void cp16(void* smem, const void* g, int srcBytes) {
    uint32_t s = (uint32_t)__cvta_generic_to_shared(smem);
    asm volatile("cp.async.cg.shared.global [%0], [%1], 16, %2;\n"
                 :: "r"(s), "l"(g), "r"(srcBytes));
}

__device__ __forceinline__ void mma_f16(float c[4],
    uint32_t a0, uint32_t a1, uint32_t a2, uint32_t a3,
    uint32_t b0, uint32_t b1)
{
    asm volatile(
        "mma.sync.aligned.m16n8k16.row.col.f32.f16.f16.f32 "
        "{%0,%1,%2,%3}, {%4,%5,%6,%7}, {%8,%9}, {%0,%1,%2,%3};"
        : "+f"(c[0]), "+f"(c[1]), "+f"(c[2]), "+f"(c[3])
        : "r"(a0), "r"(a1), "r"(a2), "r"(a3), "r"(b0), "r"(b1));
}

__device__ __forceinline__ void ldsm_x4(uint32_t& r0, uint32_t& r1,
                                        uint32_t& r2, uint32_t& r3, uint32_t addr) {
    asm volatile("ldmatrix.sync.aligned.m8n8.x4.shared.b16 {%0,%1,%2,%3}, [%4];"
                 : "=r"(r0), "=r"(r1), "=r"(r2), "=r"(r3) : "r"(addr));
}

__device__ __forceinline__ void ldsm_x2_trans(uint32_t& r0, uint32_t& r1, uint32_t addr) {
    asm volatile("ldmatrix.sync.aligned.m8n8.x2.trans.shared.b16 {%0,%1}, [%2];"
                 : "=r"(r0), "=r"(r1) : "r"(addr));
}

// ---------------- weight preconversion (vectorized, 8 elems/thread) ----------
__global__ void pack_qkv_w8(const float* __restrict__ Wq, const float* __restrict__ Wkv,
                            __half* __restrict__ dst) {
    int i = blockIdx.x * blockDim.x + threadIdx.x;            // group of 8
    const int NC8 = Dc / 8;
    if (i >= Lc * QKVSTR * NC8) return;
    int c8 = (i % NC8) * 8;
    int r  = (i / NC8) % QKVSTR;
    int l  = i / (NC8 * QKVSTR);
    const float* src;
    float sc;
    if (r < Dc) { src = Wq  + ((size_t)l * Dc + r) * Dc + c8;              sc = 0.125f; }
    else        { src = Wkv + ((size_t)l * 2 * Dc + (r - Dc)) * Dc + c8;   sc = 1.f; }
    float4 x = *(const float4*)src;
    float4 y = *(const float4*)(src + 4);
    __half2 o[4];
    o[0] = __floats2half2_rn(x.x * sc, x.y * sc);
    o[1] = __floats2half2_rn(x.z * sc, x.w * sc);
    o[2] = __floats2half2_rn(y.x * sc, y.y * sc);
    o[3] = __floats2half2_rn(y.z * sc, y.w * sc);
    *(uint4*)&dst[(size_t)i * 8] = *(uint4*)o;
}

__global__ void cvt_w8(const float* __restrict__ src, __half* __restrict__ dst, int n8) {
    int i = blockIdx.x * blockDim.x + threadIdx.x;
    if (i >= n8) return;
    float4 x = *(const float4*)(src + (size_t)i * 8);
    float4 y = *(const float4*)(src + (size_t)i * 8 + 4);
    __half2 o[4];
    o[0] = __floats2half2_rn(x.x, x.y);
    o[1] = __floats2half2_rn(x.z, x.w);
    o[2] = __floats2half2_rn(y.x, y.y);
    o[3] = __floats2half2_rn(y.z, y.w);
    *(uint4*)&dst[(size_t)i * 8] = *(uint4*)o;
}

// ---------------- embedding (4 elems/thread) ----------------
__global__ void embed_kernel(const int* __restrict__ data,
                             const float* __restrict__ we,
                             const float* __restrict__ pe,
                             float* __restrict__ h, __half* __restrict__ ht) {
    int i = blockIdx.x * blockDim.x + threadIdx.x;            // group of 4
    if (i >= M_ROWS * Dc / 4) return;
    int d4  = (i % (Dc / 4)) * 4;
    int row = i / (Dc / 4);
    int s   = row % Sc;
    int tok = data[row];
    float4 a = *(const float4*)(we + (size_t)tok * Dc + d4);
    float4 p = *(const float4*)(pe + (size_t)s   * Dc + d4);
    float4 v = make_float4(a.x + p.x, a.y + p.y, a.z + p.z, a.w + p.w);
    *(float4*)&h[(size_t)row * Dc + d4] = v;
    __half2 o[2];
    o[0] = __floats2half2_rn(v.x, v.y);
    o[1] = __floats2half2_rn(v.z, v.w);
    *(uint2*)&ht[(size_t)row * Dc + d4] = *(uint2*)o;
}

// ---------------- fp16 tensor-core GEMM (ldmatrix, TBK=32) -------------------
// C[M,N] = A[M,K] @ W[N,K]^T. outMode: 0 = fp32 out, 1 = fp16 out
#define TBM 128
#define TBN 128
#define TBK 32
#define TP 40   // halves: 80B pitch; ldmatrix 8-row footprint conflict-free

__global__ __launch_bounds__(256) void tgemm_kernel(
    const __half* __restrict__ A, const __half* __restrict__ W,
    const float* __restrict__ bias, const float* __restrict__ res,
    void* __restrict__ Cv, int M, int N, int K, int doRelu, int outMode)
{
    __shared__ __align__(16) __half As[2][TBM][TP];
    __shared__ __align__(16) __half Bs[2][TBN][TP];

    const int tid  = threadIdx.x;
    const int lane = tid & 31;
    const int warp = tid >> 5;
    const int wm   = warp >> 2;
    const int wn   = warp & 3;
    const int bm   = blockIdx.y * TBM;
    const int bn   = blockIdx.x * TBN;

    // loaders: 128 rows x 64B per tile = 512 x 16B chunks; 2 per thread
    const int lrow0 = tid >> 1;               // chunks c = tid + p*256: row = c>>2
    (void)lrow0;

    const uint32_t asBase = (uint32_t)__cvta_generic_to_shared(&As[0][0][0]);
    const uint32_t bsBase = (uint32_t)__cvta_generic_to_shared(&Bs[0][0][0]);

    float acc[4][4][4];
    #pragma unroll
    for (int i = 0; i < 4; i++)
        #pragma unroll
        for (int j = 0; j < 4; j++)
            #pragma unroll
            for (int t = 0; t < 4; t++) acc[i][j][t] = 0.f;

    const int KT = K / TBK;

    // prologue
    #pragma unroll
    for (int p = 0; p < 2; p++) {
        int c = tid + p * 256;
        int r = c >> 2, hoff = (c & 3) * 8;
        cp16(&As[0][r][hoff], A + (size_t)(bm + r) * K + hoff, 16);
        int gn = bn + r;
        int ok = (gn < N) ? 16 : 0;
        int gc = (gn < N) ? gn : (N - 1);
        cp16(&Bs[0][r][hoff], W + (size_t)gc * K + hoff, ok);
    }
    asm volatile("cp.async.commit_group;\n");

    const int r8  = lane & 7;
    const int sel = lane >> 3;               // 0..3

    for (int t = 0; t < KT; t++) {
        asm volatile("cp.async.wait_group 0;\n");
        __syncthreads();

        if (t + 1 < KT) {
            int nb = (t + 1) & 1;
            int k0 = (t + 1) * TBK;
            #pragma unroll
            for (int p = 0; p < 2; p++) {
                int c = tid + p * 256;
                int r = c >> 2, hoff = (c & 3) * 8;
                cp16(&As[nb][r][hoff], A + (size_t)(bm + r) * K + k0 + hoff, 16);
                int gn = bn + r;
                int ok = (gn < N) ? 16 : 0;
                int gc = (gn < N) ? gn : (N - 1);
                cp16(&Bs[nb][r][hoff], W + (size_t)gc * K + k0 + hoff, ok);
            }
            asm volatile("cp.async.commit_group;\n");
        }

        const int buf = t & 1;
        #pragma unroll
        for (int ks = 0; ks < 2; ks++) {
            const int kb = ks * 16;

            uint32_t af[4][4], bf[4][2];
            // A fragments: 4 ldmatrix.x4 (rows wm*64 + mi*16 .. +15, k kb..kb+15)
            #pragma unroll
            for (int mi = 0; mi < 4; mi++) {
                int row  = wm * 64 + mi * 16 + r8 + ((sel & 1) << 3);
                int colh = kb + ((sel >> 1) << 3);
                uint32_t addr = asBase + (((buf * TBM + row) * TP + colh) << 1);
                ldsm_x4(af[mi][0], af[mi][1], af[mi][2], af[mi][3], addr);
            }
            // B fragments: 2 ldmatrix.x4, each covers two n-octets
            #pragma unroll
            for (int nj = 0; nj < 2; nj++) {
                int row  = wn * 32 + nj * 16 + r8 + ((sel >> 1) << 3);
                int colh = kb + ((sel & 1) << 3);
                uint32_t addr = bsBase + (((buf * TBN + row) * TP + colh) << 1);
                ldsm_x4(bf[nj*2][0], bf[nj*2][1], bf[nj*2+1][0], bf[nj*2+1][1], addr);
            }
            #pragma unroll
            for (int mi = 0; mi < 4; mi++)
                #pragma unroll
                for (int ni = 0; ni < 4; ni++)
                    mma_f16(acc[mi][ni], af[mi][0], af[mi][1], af[mi][2], af[mi][3],
                            bf[ni][0], bf[ni][1]);
        }
        __syncthreads();
    }

    const int lr = lane >> 2;
    const int lc = (lane & 3) * 2;
    #pragma unroll
    for (int mi = 0; mi < 4; mi++) {
        int r0 = bm + wm * 64 + mi * 16 + lr;
        #pragma unroll
        for (int ni = 0; ni < 4; ni++) {
            int c0 = bn + wn * 32 + ni * 8 + lc;
            if (c0 >= N) continue;
            float v0 = acc[mi][ni][0], v1 = acc[mi][ni][1];
            float v2 = acc[mi][ni][2], v3 = acc[mi][ni][3];
            if (bias) {
                float b0 = bias[c0], b1 = bias[c0 + 1];
                v0 += b0; v1 += b1; v2 += b0; v3 += b1;
            }
            if (res) {
                v0 += res[(size_t)r0 * N + c0];
                v1 += res[(size_t)r0 * N + c0 + 1];
                v2 += res[(size_t)(r0 + 8) * N + c0];
                v3 += res[(size_t)(r0 + 8) * N + c0 + 1];
            }
            if (doRelu) {
                v0 = fmaxf(v0, 0.f); v1 = fmaxf(v1, 0.f);
                v2 = fmaxf(v2, 0.f); v3 = fmaxf(v3, 0.f);
            }
            if (outMode == 0) {
                float* C = (float*)Cv;
                *(float2*)&C[(size_t)r0 * N + c0]       = make_float2(v0, v1);
                *(float2*)&C[(size_t)(r0 + 8) * N + c0] = make_float2(v2, v3);
            } else {
                __half* C = (__half*)Cv;
                *(__half2*)&C[(size_t)r0 * N + c0]       = __floats2half2_rn(v0, v1);
                *(__half2*)&C[(size_t)(r0 + 8) * N + c0] = __floats2half2_rn(v2, v3);
            }
        }
    }
}

// ---------------- fp16 tensor-core flash attention (unchanged from R8) -------
#define APH 72
#define FATTN_SMEM (6 * 64 * APH * 2)

extern __shared__ __half attn_smem[];

__global__ __launch_bounds__(128) void fattn_tc(
    const __half* __restrict__ Q, const __half* __restrict__ Kb,
    const __half* __restrict__ Vb, __half* __restrict__ O)
{
    __half* Qs = attn_smem;
    __half* Ks = Qs + 64 * APH;
    __half* Vk = Ks + 2 * 64 * APH;
    __half* Ps = Vk + 2 * 64 * APH;

    const int qt = (gridDim.x - 1) - blockIdx.x;
    const int h  = blockIdx.y, b = blockIdx.z;
    const int q0 = qt * 64;
    const int tid  = threadIdx.x;
    const int lane = tid & 31;
    const int warp = tid >> 5;

    const int OST = Hc * DHc;

    const int r0  = warp * 16 + (lane >> 2);
    const int kh  = (lane & 3) * 2;
    const int ls4 = lane >> 2;

    #pragma unroll
    for (int p = 0; p < 4; p++) {
        int c = tid + p * 128;
        int r = c >> 3, d8 = (c & 7) * 8;
        float4 v = *(const float4*)(Q + (size_t)(b * Sc + q0 + r) * QKVSTR + h * DHc + d8);
        *(float4*)&Qs[r * APH + d8] = v;
    }

    float o_acc[8][4];
    #pragma unroll
    for (int n = 0; n < 8; n++)
        #pragma unroll
        for (int t = 0; t < 4; t++) o_acc[n][t] = 0.f;
    float m0 = -1e30f, m1 = -1e30f, l0 = 0.f, l1 = 0.f;

    const int nt = qt + 1;
    const size_t kvrow0 = (size_t)(b * Sc) * QKVSTR + h * DHc;

    #pragma unroll
    for (int p = 0; p < 4; p++) {
        int c = tid + p * 128;
        int r = c >> 3, d8 = (c & 7) * 8;
        cp16(&Ks[r * APH + d8], Kb + kvrow0 + (size_t)r * QKVSTR + d8, 16);
        cp16(&Vk[r * APH + d8], Vb + kvrow0 + (size_t)r * QKVSTR + d8, 16);
    }
    asm volatile("cp.async.commit_group;\n");

    for (int kt = 0; kt < nt; kt++) {
        asm volatile("cp.async.wait_group 0;\n");
        __syncthreads();

        const int buf = kt & 1;
        if (kt + 1 < nt) {
            const int nb = buf ^ 1;
            const size_t base = kvrow0 + (size_t)(kt + 1) * 64 * QKVSTR;
            #pragma unroll
            for (int p = 0; p < 4; p++) {
                int c = tid + p * 128;
                int r = c >> 3, d8 = (c & 7) * 8;
                cp16(&Ks[nb * 64 * APH + r * APH + d8], Kb + base + (size_t)r * QKVSTR + d8, 16);
                cp16(&Vk[nb * 64 * APH + r * APH + d8], Vb + base + (size_t)r * QKVSTR + d8, 16);
            }
        }
        asm volatile("cp.async.commit_group;\n");

        const __half* Kt = Ks + buf * 64 * APH;
        const __half* Vt = Vk + buf * 64 * APH;

        float sacc[8][4];
        #pragma unroll
        for (int n = 0; n < 8; n++)
            #pragma unroll
            for (int t = 0; t < 4; t++) sacc[n][t] = 0.f;

        #pragma unroll
        for (int ks = 0; ks < 4; ks++) {
            const int kb = ks * 16;
            uint32_t a0 = *(const uint32_t*)&Qs[ r0      * APH + kb + kh];
            uint32_t a1 = *(const uint32_t*)&Qs[(r0 + 8) * APH + kb + kh];
            uint32_t a2 = *(const uint32_t*)&Qs[ r0      * APH + kb + kh + 8];
            uint32_t a3 = *(const uint32_t*)&Qs[(r0 + 8) * APH + kb + kh + 8];
            #pragma unroll
            for (int n = 0; n < 8; n++) {
                const int nr = n * 8 + ls4;
                uint32_t b0 = *(const uint32_t*)&Kt[nr * APH + kb + kh];
                uint32_t b1 = *(const uint32_t*)&Kt[nr * APH + kb + kh + 8];
                mma_f16(sacc[n], a0, a1, a2, a3, b0, b1);
            }
        }

        if (kt == qt) {
            #pragma unroll
            for (int n = 0; n < 8; n++) {
                const int c0 = n * 8 + (lane & 3) * 2;
                if (c0     > r0)     sacc[n][0] = -1e30f;
                if (c0 + 1 > r0)     sacc[n][1] = -1e30f;
                if (c0     > r0 + 8) sacc[n][2] = -1e30f;
                if (c0 + 1 > r0 + 8) sacc[n][3] = -1e30f;
            }
        }

        float mx0 = -1e30f, mx1 = -1e30f;
        #pragma unroll
        for (int n = 0; n < 8; n++) {
            mx0 = fmaxf(mx0, fmaxf(sacc[n][0], sacc[n][1]));
            mx1 = fmaxf(mx1, fmaxf(sacc[n][2], sacc[n][3]));
        }
        mx0 = fmaxf(mx0, __shfl_xor_sync(0xffffffffu, mx0, 1));
        mx0 = fmaxf(mx0, __shfl_xor_sync(0xffffffffu, mx0, 2));
        mx1 = fmaxf(mx1, __shfl_xor_sync(0xffffffffu, mx1, 1));
        mx1 = fmaxf(mx1, __shfl_xor_sync(0xffffffffu, mx1, 2));

        const float mn0 = fmaxf(m0, mx0);
        const float mn1 = fmaxf(m1, mx1);
        const float cr0 = __expf(m0 - mn0);
        const float cr1 = __expf(m1 - mn1);
        float s0 = 0.f, s1 = 0.f;
        #pragma unroll
        for (int n = 0; n < 8; n++) {
            float p00 = __expf(sacc[n][0] - mn0);
            float p01 = __expf(sacc[n][1] - mn0);
            float p10 = __expf(sacc[n][2] - mn1);
            float p11 = __expf(sacc[n][3] - mn1);
            s0 += p00 + p01;
            s1 += p10 + p11;
            const int c0 = n * 8 + (lane & 3) * 2;
            *(__half2*)&Ps[ r0      * APH + c0] = __floats2half2_rn(p00, p01);
            *(__half2*)&Ps[(r0 + 8) * APH + c0] = __floats2half2_rn(p10, p11);
        }
        s0 += __shfl_xor_sync(0xffffffffu, s0, 1);
        s0 += __shfl_xor_sync(0xffffffffu, s0, 2);
        s1 += __shfl_xor_sync(0xffffffffu, s1, 1);
        s1 += __shfl_xor_sync(0xffffffffu, s1, 2);

        l0 = l0 * cr0 + s0;  m0 = mn0;
        l1 = l1 * cr1 + s1;  m1 = mn1;
        #pragma unroll
        for (int n = 0; n < 8; n++) {
            o_acc[n][0] *= cr0; o_acc[n][1] *= cr0;
            o_acc[n][2] *= cr1; o_acc[n][3] *= cr1;
        }
        __syncwarp();

        #pragma unroll
        for (int ks = 0; ks < 4; ks++) {
            const int kb = ks * 16;
            uint32_t a0 = *(const uint32_t*)&Ps[ r0      * APH + kb + kh];
            uint32_t a1 = *(const uint32_t*)&Ps[(r0 + 8) * APH + kb + kh];
            uint32_t a2 = *(const uint32_t*)&Ps[ r0      * APH + kb + kh + 8];
            uint32_t a3 = *(const uint32_t*)&Ps[(r0 + 8) * APH + kb + kh + 8];
            uint32_t base = (uint32_t)__cvta_generic_to_shared(
                                &Vt[(kb + (lane & 15)) * APH]);
            #pragma unroll
            for (int n = 0; n < 8; n++) {
                uint32_t b0, b1;
                ldsm_x2_trans(b0, b1, base + n * 16);
                mma_f16(o_acc[n], a0, a1, a2, a3, b0, b1);
            }
        }
    }

    const float inv0 = 1.f / l0;
    const float inv1 = 1.f / l1;
    #pragma unroll
    for (int n = 0; n < 8; n++) {
        const int c0 = n * 8 + (lane & 3) * 2;
        size_t o0 = (size_t)(b * Sc + q0 + r0)     * OST + h * DHc + c0;
        size_t o1 = (size_t)(b * Sc + q0 + r0 + 8) * OST + h * DHc + c0;
        *(__half2*)&O[o0] = __floats2half2_rn(o_acc[n][0] * inv0, o_acc[n][1] * inv0);
        *(__half2*)&O[o1] = __floats2half2_rn(o_acc[n][2] * inv1, o_acc[n][3] * inv1);
    }
}

// ---------------- LayerNorm over D=512 (dual output) --------------------------
__global__ void ln_kernel(const float* __restrict__ X, const float* __restrict__ g,
                          const float* __restrict__ bta, float* __restrict__ Y,
                          __half* __restrict__ Yt) {
    int row = blockIdx.x;
    const float* x = X + (size_t)row * Dc;
    float*  y  = Y  + (size_t)row * Dc;
    __half* yt = Yt + (size_t)row * Dc;
    int tid = threadIdx.x;

    float v[4];
    float sum = 0.f;
    #pragma unroll
    for (int i = 0; i < 4; i++) { v[i] = x[tid + i*128]; sum += v[i]; }

    __shared__ float red[4];
    #pragma unroll
    for (int off = 16; off; off >>= 1) sum += __shfl_xor_sync(0xffffffffu, sum, off);
    if ((tid & 31) == 0) red[tid >> 5] = sum;
    __syncthreads();
    sum = red[0] + red[1] + red[2] + red[3];
    float mean = sum * (1.f / Dc);

    float sq = 0.f;
    #pragma unroll
    for (int i = 0; i < 4; i++) { float d = v[i] - mean; sq += d * d; }
    __shared__ float red2[4];
    #pragma unroll
    for (int off = 16; off; off >>= 1) sq += __shfl_xor_sync(0xffffffffu, sq, off);
    if ((tid & 31) == 0) red2[tid >> 5] = sq;
    __syncthreads();
    sq = red2[0] + red2[1] + red2[2] + red2[3];
    float rstd = rsqrtf(sq * (1.f / Dc) + 1e-5f);

    #pragma unroll
    for (int i = 0; i < 4; i++) {
        int d = tid + i*128;
        float o = (v[i] - mean) * rstd * g[d] + bta[d];
        y[d]  = o;
        yt[d] = __float2half_rn(o);
    }
}

// ---------------- launch ----------------------------------------------------
extern "C" void kernel_launch(void* const* d_in, const int* in_sizes, int n_in,
                              void* d_out, int out_size) {
    const int*   data = (const int*)  d_in[0];
    const float* we   = (const float*)d_in[1];
    const float* pe   = (const float*)d_in[2];
    const float* Wq   = (const float*)d_in[3];
    const float* Wkv  = (const float*)d_in[4];
    const float* Wo   = (const float*)d_in[5];
    const float* g1   = (const float*)d_in[6];
    const float* bl1  = (const float*)d_in[7];
    const float* W1   = (const float*)d_in[8];
    const float* bf1  = (const float*)d_in[9];
    const float* W2   = (const float*)d_in[10];
    const float* bf2  = (const float*)d_in[11];
    const float* g2   = (const float*)d_in[12];
    const float* bl2  = (const float*)d_in[13];
    const float* outb = (const float*)d_in[14];
    float* out = (float*)d_out;

    float *h, *tmp;
    __half *ht, *qkv, *aot, *fft;
    __half *wqkv, *wo_t, *w1_t, *w2_t, *we_t;
    cudaGetSymbolAddress((void**)&h,    g_h);
    cudaGetSymbolAddress((void**)&ht,   g_ht);
    cudaGetSymbolAddress((void**)&qkv,  g_qkv);
    cudaGetSymbolAddress((void**)&aot,  g_aot);
    cudaGetSymbolAddress((void**)&tmp,  g_tmp);
    cudaGetSymbolAddress((void**)&fft,  g_fft);
    cudaGetSymbolAddress((void**)&wqkv, g_wqkv);
    cudaGetSymbolAddress((void**)&wo_t, g_wo_t);
    cudaGetSymbolAddress((void**)&w1_t, g_w1_t);
    cudaGetSymbolAddress((void**)&w2_t, g_w2_t);
    cudaGetSymbolAddress((void**)&we_t, g_we_t);

    cudaFuncSetAttribute(fattn_tc, cudaFuncAttributeMaxDynamicSharedMemorySize, FATTN_SMEM);

    // weight preconversion (fp16, vectorized)
    {
        int n8;
        n8 = Lc * QKVSTR * Dc / 8;  pack_qkv_w8<<<(n8 + 255)/256, 256>>>(Wq, Wkv, wqkv);
        n8 = Lc * Dc * Dc / 8;      cvt_w8<<<(n8 + 255)/256, 256>>>(Wo, wo_t, n8);
        n8 = Lc * DIc * Dc / 8;     cvt_w8<<<(n8 + 255)/256, 256>>>(W1, w1_t, n8);
        n8 = Lc * Dc * DIc / 8;     cvt_w8<<<(n8 + 255)/256, 256>>>(W2, w2_t, n8);
        n8 = Vc * Dc / 8;           cvt_w8<<<(n8 + 255)/256, 256>>>(we, we_t, n8);
    }

    embed_kernel<<<(M_ROWS*Dc/4 + 255)/256, 256>>>(data, we, pe, h, ht);

    dim3 gsD  (( Dc     + 127)/128, M_ROWS/128);
    dim3 gsQKV((QKVSTR  + 127)/128, M_ROWS/128);
    dim3 gsDI (( DIc    + 127)/128, M_ROWS/128);
    dim3 gsV  (( Vc     + 127)/128, M_ROWS/128);
    dim3 gsA  (Sc/64, Hc, Bc);

    for (int l = 0; l < Lc; l++) {
        tgemm_kernel<<<gsQKV, 256>>>(ht, wqkv + (size_t)l*QKVSTR*Dc, nullptr, nullptr,
                                     qkv, M_ROWS, QKVSTR, Dc, 0, 1);

        fattn_tc<<<gsA, 128, FATTN_SMEM>>>(qkv, qkv + Dc, qkv + 2*Dc, aot);

        tgemm_kernel<<<gsD, 256>>>(aot, wo_t + (size_t)l*Dc*Dc, nullptr, h, tmp,
                                   M_ROWS, Dc, Dc, 0, 0);
        ln_kernel<<<M_ROWS, 128>>>(tmp, g1 + (size_t)l*Dc, bl1 + (size_t)l*Dc, h, ht);

        tgemm_kernel<<<gsDI, 256>>>(ht, w1_t + (size_t)l*DIc*Dc, bf1 + (size_t)l*DIc, nullptr,
                                    fft, M_ROWS, DIc, Dc, 1, 1);
        tgemm_kernel<<<gsD, 256>>>(fft, w2_t + (size_t)l*Dc*DIc, bf2 + (size_t)l*Dc, h,
                                   tmp, M_ROWS, Dc, DIc, 0, 0);
        ln_kernel<<<M_ROWS, 128>>>(tmp, g2 + (size_t)l*Dc, bl2 + (size_t)l*Dc, h, ht);
    }

    tgemm_kernel<<<gsV, 256>>>(ht, we_t, outb, nullptr, out, M_ROWS, Vc, Dc, 0, 0);
}

// round 10
// speedup vs baseline: 2.1439x; 1.0464x over previous
#include <cuda_runtime.h>
#include <cuda_fp16.h>
#include <math.h>
#include <stdint.h>

#define Bc 4
#define Sc 1024
#define Dc 512
#define Hc 8
#define DHc 64
#define DIc 2048
#define Lc 12
#define Vc 10000
#define M_ROWS (Bc*Sc)   /* 4096 */
#define QKVSTR (3*Dc)    /* 1536 */

// ---------------- scratch (no allocations allowed) ----------------
__device__ float  g_h   [M_ROWS*Dc];
__device__ __half g_ht  [M_ROWS*Dc];
__device__ __half g_qkv [M_ROWS*QKVSTR];
__device__ __half g_aot [M_ROWS*Dc];
__device__ float  g_tmp [M_ROWS*Dc];
__device__ __half g_fft [M_ROWS*DIc];
__device__ __half g_wqkv[Lc*QKVSTR*Dc];
__device__ __half g_wo_t[Lc*Dc*Dc];
__device__ __half g_w1_t[Lc*DIc*Dc];
__device__ __half g_w2_t[Lc*Dc*DIc];
__device__ __half g_we_t[Vc*Dc];

// ---------------- helpers ----------------------------------------------------
__device__ __forceinline__ void cp16(void* smem, const void* g, int srcBytes) {
    uint32_t s = (uint32_t)__cvta_generic_to_shared(smem);
    asm volatile("cp.async.cg.shared.global [%0], [%1], 16, %2;\n"
                 :: "r"(s), "l"(g), "r"(srcBytes));
}

__device__ __forceinline__ void mma_f16(float c[4],
    uint32_t a0, uint32_t a1, uint32_t a2, uint32_t a3,
    uint32_t b0, uint32_t b1)
{
    asm volatile(
        "mma.sync.aligned.m16n8k16.row.col.f32.f16.f16.f32 "
        "{%0,%1,%2,%3}, {%4,%5,%6,%7}, {%8,%9}, {%0,%1,%2,%3};"
        : "+f"(c[0]), "+f"(c[1]), "+f"(c[2]), "+f"(c[3])
        : "r"(a0), "r"(a1), "r"(a2), "r"(a3), "r"(b0), "r"(b1));
}

__device__ __forceinline__ void ldsm_x4(uint32_t& r0, uint32_t& r1,
                                        uint32_t& r2, uint32_t& r3, uint32_t addr) {
    asm volatile("ldmatrix.sync.aligned.m8n8.x4.shared.b16 {%0,%1,%2,%3}, [%4];"
                 : "=r"(r0), "=r"(r1), "=r"(r2), "=r"(r3) : "r"(addr));
}

__device__ __forceinline__ void ldsm_x2_trans(uint32_t& r0, uint32_t& r1, uint32_t addr) {
    asm volatile("ldmatrix.sync.aligned.m8n8.x2.trans.shared.b16 {%0,%1}, [%2];"
                 : "=r"(r0), "=r"(r1) : "r"(addr));
}

// ---------------- weight preconversion (vectorized) ---------------------------
__global__ void pack_qkv_w8(const float* __restrict__ Wq, const float* __restrict__ Wkv,
                            __half* __restrict__ dst) {
    int i = blockIdx.x * blockDim.x + threadIdx.x;
    const int NC8 = Dc / 8;
    if (i >= Lc * QKVSTR * NC8) return;
    int c8 = (i % NC8) * 8;
    int r  = (i / NC8) % QKVSTR;
    int l  = i / (NC8 * QKVSTR);
    const float* src;
    float sc;
    if (r < Dc) { src = Wq  + ((size_t)l * Dc + r) * Dc + c8;              sc = 0.125f; }
    else        { src = Wkv + ((size_t)l * 2 * Dc + (r - Dc)) * Dc + c8;   sc = 1.f; }
    float4 x = *(const float4*)src;
    float4 y = *(const float4*)(src + 4);
    __half2 o[4];
    o[0] = __floats2half2_rn(x.x * sc, x.y * sc);
    o[1] = __floats2half2_rn(x.z * sc, x.w * sc);
    o[2] = __floats2half2_rn(y.x * sc, y.y * sc);
    o[3] = __floats2half2_rn(y.z * sc, y.w * sc);
    *(uint4*)&dst[(size_t)i * 8] = *(uint4*)o;
}

__global__ void cvt_w8(const float* __restrict__ src, __half* __restrict__ dst, int n8) {
    int i = blockIdx.x * blockDim.x + threadIdx.x;
    if (i >= n8) return;
    float4 x = *(const float4*)(src + (size_t)i * 8);
    float4 y = *(const float4*)(src + (size_t)i * 8 + 4);
    __half2 o[4];
    o[0] = __floats2half2_rn(x.x, x.y);
    o[1] = __floats2half2_rn(x.z, x.w);
    o[2] = __floats2half2_rn(y.x, y.y);
    o[3] = __floats2half2_rn(y.z, y.w);
    *(uint4*)&dst[(size_t)i * 8] = *(uint4*)o;
}

// ---------------- embedding (4 elems/thread) ----------------
__global__ void embed_kernel(const int* __restrict__ data,
                             const float* __restrict__ we,
                             const float* __restrict__ pe,
                             float* __restrict__ h, __half* __restrict__ ht) {
    int i = blockIdx.x * blockDim.x + threadIdx.x;
    if (i >= M_ROWS * Dc / 4) return;
    int d4  = (i % (Dc / 4)) * 4;
    int row = i / (Dc / 4);
    int s   = row % Sc;
    int tok = data[row];
    float4 a = *(const float4*)(we + (size_t)tok * Dc + d4);
    float4 p = *(const float4*)(pe + (size_t)s   * Dc + d4);
    float4 v = make_float4(a.x + p.x, a.y + p.y, a.z + p.z, a.w + p.w);
    *(float4*)&h[(size_t)row * Dc + d4] = v;
    __half2 o[2];
    o[0] = __floats2half2_rn(v.x, v.y);
    o[1] = __floats2half2_rn(v.z, v.w);
    *(uint2*)&ht[(size_t)row * Dc + d4] = *(uint2*)o;
}

// ============ tgemm64: TBM=64, TBN=128, 3-stage pipeline, 1 sync/iter =========
// Requires: M % 64 == 0, N % 128 == 0, K % 32 == 0.
#define T2M 64
#define T2N 128
#define T2K 32
#define TP 40

__global__ __launch_bounds__(256) void tgemm64_kernel(
    const __half* __restrict__ A, const __half* __restrict__ W,
    const float* __restrict__ bias, const float* __restrict__ res,
    void* __restrict__ Cv, int M, int N, int K, int doRelu, int outMode)
{
    __shared__ __align__(16) __half As[3][T2M][TP];
    __shared__ __align__(16) __half Bs[3][T2N][TP];

    const int tid  = threadIdx.x;
    const int lane = tid & 31;
    const int warp = tid >> 5;
    const int wm   = warp >> 2;          // 0..1 -> 32 rows each
    const int wn   = warp & 3;           // 0..3 -> 32 cols each
    const int bm   = blockIdx.y * T2M;
    const int bn   = blockIdx.x * T2N;

    const uint32_t asBase = (uint32_t)__cvta_generic_to_shared(&As[0][0][0]);
    const uint32_t bsBase = (uint32_t)__cvta_generic_to_shared(&Bs[0][0][0]);

    float acc[2][4][4];
    #pragma unroll
    for (int i = 0; i < 2; i++)
        #pragma unroll
        for (int j = 0; j < 4; j++)
            #pragma unroll
            for (int t = 0; t < 4; t++) acc[i][j][t] = 0.f;

    const int KT = K / T2K;

    // loader mapping: A: chunk tid (256 = 64 rows x 4); B: chunks tid, tid+256
    const int rA  = tid >> 2, hA = (tid & 3) * 8;

    // prologue: stages 0,1
    #pragma unroll
    for (int s = 0; s < 2; s++) {
        int k0 = s * T2K;
        cp16(&As[s][rA][hA], A + (size_t)(bm + rA) * K + k0 + hA, 16);
        #pragma unroll
        for (int p = 0; p < 2; p++) {
            int c = tid + p * 256;
            int r = c >> 2, hf = (c & 3) * 8;
            cp16(&Bs[s][r][hf], W + (size_t)(bn + r) * K + k0 + hf, 16);
        }
        asm volatile("cp.async.commit_group;\n");
    }

    const int r8  = lane & 7;
    const int sel = lane >> 3;

    for (int t = 0; t < KT; t++) {
        asm volatile("cp.async.wait_group 1;\n");
        __syncthreads();

        // prefetch stage t+2 (overwrites stage computed at t-1; safe after sync)
        {
            int tp = t + 2;
            if (tp < KT) {
                int sb = tp % 3;
                int k0 = tp * T2K;
                cp16(&As[sb][rA][hA], A + (size_t)(bm + rA) * K + k0 + hA, 16);
                #pragma unroll
                for (int p = 0; p < 2; p++) {
                    int c = tid + p * 256;
                    int r = c >> 2, hf = (c & 3) * 8;
                    cp16(&Bs[sb][r][hf], W + (size_t)(bn + r) * K + k0 + hf, 16);
                }
            }
            asm volatile("cp.async.commit_group;\n");
        }

        const int buf = t % 3;
        #pragma unroll
        for (int ks = 0; ks < 2; ks++) {
            const int kb = ks * 16;
            uint32_t af[2][4], bf[4][2];
            #pragma unroll
            for (int mi = 0; mi < 2; mi++) {
                int row  = wm * 32 + mi * 16 + r8 + ((sel & 1) << 3);
                int colh = kb + ((sel >> 1) << 3);
                uint32_t addr = asBase + (((buf * T2M + row) * TP + colh) << 1);
                ldsm_x4(af[mi][0], af[mi][1], af[mi][2], af[mi][3], addr);
            }
            #pragma unroll
            for (int nj = 0; nj < 2; nj++) {
                int row  = wn * 32 + nj * 16 + r8 + ((sel >> 1) << 3);
                int colh = kb + ((sel & 1) << 3);
                uint32_t addr = bsBase + (((buf * T2N + row) * TP + colh) << 1);
                ldsm_x4(bf[nj*2][0], bf[nj*2][1], bf[nj*2+1][0], bf[nj*2+1][1], addr);
            }
            #pragma unroll
            for (int mi = 0; mi < 2; mi++)
                #pragma unroll
                for (int ni = 0; ni < 4; ni++)
                    mma_f16(acc[mi][ni], af[mi][0], af[mi][1], af[mi][2], af[mi][3],
                            bf[ni][0], bf[ni][1]);
        }
    }

    const int lr = lane >> 2;
    const int lc = (lane & 3) * 2;
    #pragma unroll
    for (int mi = 0; mi < 2; mi++) {
        int r0 = bm + wm * 32 + mi * 16 + lr;
        #pragma unroll
        for (int ni = 0; ni < 4; ni++) {
            int c0 = bn + wn * 32 + ni * 8 + lc;
            float v0 = acc[mi][ni][0], v1 = acc[mi][ni][1];
            float v2 = acc[mi][ni][2], v3 = acc[mi][ni][3];
            if (bias) {
                float b0 = bias[c0], b1 = bias[c0 + 1];
                v0 += b0; v1 += b1; v2 += b0; v3 += b1;
            }
            if (res) {
                v0 += res[(size_t)r0 * N + c0];
                v1 += res[(size_t)r0 * N + c0 + 1];
                v2 += res[(size_t)(r0 + 8) * N + c0];
                v3 += res[(size_t)(r0 + 8) * N + c0 + 1];
            }
            if (doRelu) {
                v0 = fmaxf(v0, 0.f); v1 = fmaxf(v1, 0.f);
                v2 = fmaxf(v2, 0.f); v3 = fmaxf(v3, 0.f);
            }
            if (outMode == 0) {
                float* C = (float*)Cv;
                *(float2*)&C[(size_t)r0 * N + c0]       = make_float2(v0, v1);
                *(float2*)&C[(size_t)(r0 + 8) * N + c0] = make_float2(v2, v3);
            } else {
                __half* C = (__half*)Cv;
                *(__half2*)&C[(size_t)r0 * N + c0]       = __floats2half2_rn(v0, v1);
                *(__half2*)&C[(size_t)(r0 + 8) * N + c0] = __floats2half2_rn(v2, v3);
            }
        }
    }
}

// ============ tgemm128: proven 128x128 TBK=32 kernel (logits) ================
#define TBM 128
#define TBN 128
#define TBK 32

__global__ __launch_bounds__(256) void tgemm_kernel(
    const __half* __restrict__ A, const __half* __restrict__ W,
    const float* __restrict__ bias, const float* __restrict__ res,
    void* __restrict__ Cv, int M, int N, int K, int doRelu, int outMode)
{
    __shared__ __align__(16) __half As[2][TBM][TP];
    __shared__ __align__(16) __half Bs[2][TBN][TP];

    const int tid  = threadIdx.x;
    const int lane = tid & 31;
    const int warp = tid >> 5;
    const int wm   = warp >> 2;
    const int wn   = warp & 3;
    const int bm   = blockIdx.y * TBM;
    const int bn   = blockIdx.x * TBN;

    const uint32_t asBase = (uint32_t)__cvta_generic_to_shared(&As[0][0][0]);
    const uint32_t bsBase = (uint32_t)__cvta_generic_to_shared(&Bs[0][0][0]);

    float acc[4][4][4];
    #pragma unroll
    for (int i = 0; i < 4; i++)
        #pragma unroll
        for (int j = 0; j < 4; j++)
            #pragma unroll
            for (int t = 0; t < 4; t++) acc[i][j][t] = 0.f;

    const int KT = K / TBK;

    #pragma unroll
    for (int p = 0; p < 2; p++) {
        int c = tid + p * 256;
        int r = c >> 2, hoff = (c & 3) * 8;
        cp16(&As[0][r][hoff], A + (size_t)(bm + r) * K + hoff, 16);
        int gn = bn + r;
        int ok = (gn < N) ? 16 : 0;
        int gc = (gn < N) ? gn : (N - 1);
        cp16(&Bs[0][r][hoff], W + (size_t)gc * K + hoff, ok);
    }
    asm volatile("cp.async.commit_group;\n");

    const int r8  = lane & 7;
    const int sel = lane >> 3;

    for (int t = 0; t < KT; t++) {
        asm volatile("cp.async.wait_group 0;\n");
        __syncthreads();

        if (t + 1 < KT) {
            int nb = (t + 1) & 1;
            int k0 = (t + 1) * TBK;
            #pragma unroll
            for (int p = 0; p < 2; p++) {
                int c = tid + p * 256;
                int r = c >> 2, hoff = (c & 3) * 8;
                cp16(&As[nb][r][hoff], A + (size_t)(bm + r) * K + k0 + hoff, 16);
                int gn = bn + r;
                int ok = (gn < N) ? 16 : 0;
                int gc = (gn < N) ? gn : (N - 1);
                cp16(&Bs[nb][r][hoff], W + (size_t)gc * K + k0 + hoff, ok);
            }
            asm volatile("cp.async.commit_group;\n");
        }

        const int buf = t & 1;
        #pragma unroll
        for (int ks = 0; ks < 2; ks++) {
            const int kb = ks * 16;
            uint32_t af[4][4], bf[4][2];
            #pragma unroll
            for (int mi = 0; mi < 4; mi++) {
                int row  = wm * 64 + mi * 16 + r8 + ((sel & 1) << 3);
                int colh = kb + ((sel >> 1) << 3);
                uint32_t addr = asBase + (((buf * TBM + row) * TP + colh) << 1);
                ldsm_x4(af[mi][0], af[mi][1], af[mi][2], af[mi][3], addr);
            }
            #pragma unroll
            for (int nj = 0; nj < 2; nj++) {
                int row  = wn * 32 + nj * 16 + r8 + ((sel >> 1) << 3);
                int colh = kb + ((sel & 1) << 3);
                uint32_t addr = bsBase + (((buf * TBN + row) * TP + colh) << 1);
                ldsm_x4(bf[nj*2][0], bf[nj*2][1], bf[nj*2+1][0], bf[nj*2+1][1], addr);
            }
            #pragma unroll
            for (int mi = 0; mi < 4; mi++)
                #pragma unroll
                for (int ni = 0; ni < 4; ni++)
                    mma_f16(acc[mi][ni], af[mi][0], af[mi][1], af[mi][2], af[mi][3],
                            bf[ni][0], bf[ni][1]);
        }
        __syncthreads();
    }

    const int lr = lane >> 2;
    const int lc = (lane & 3) * 2;
    #pragma unroll
    for (int mi = 0; mi < 4; mi++) {
        int r0 = bm + wm * 64 + mi * 16 + lr;
        #pragma unroll
        for (int ni = 0; ni < 4; ni++) {
            int c0 = bn + wn * 32 + ni * 8 + lc;
            if (c0 >= N) continue;
            float v0 = acc[mi][ni][0], v1 = acc[mi][ni][1];
            float v2 = acc[mi][ni][2], v3 = acc[mi][ni][3];
            if (bias) {
                float b0 = bias[c0], b1 = bias[c0 + 1];
                v0 += b0; v1 += b1; v2 += b0; v3 += b1;
            }
            if (res) {
                v0 += res[(size_t)r0 * N + c0];
                v1 += res[(size_t)r0 * N + c0 + 1];
                v2 += res[(size_t)(r0 + 8) * N + c0];
                v3 += res[(size_t)(r0 + 8) * N + c0 + 1];
            }
            if (doRelu) {
                v0 = fmaxf(v0, 0.f); v1 = fmaxf(v1, 0.f);
                v2 = fmaxf(v2, 0.f); v3 = fmaxf(v3, 0.f);
            }
            if (outMode == 0) {
                float* C = (float*)Cv;
                *(float2*)&C[(size_t)r0 * N + c0]       = make_float2(v0, v1);
                *(float2*)&C[(size_t)(r0 + 8) * N + c0] = make_float2(v2, v3);
            } else {
                __half* C = (__half*)Cv;
                *(__half2*)&C[(size_t)r0 * N + c0]       = __floats2half2_rn(v0, v1);
                *(__half2*)&C[(size_t)(r0 + 8) * N + c0] = __floats2half2_rn(v2, v3);
            }
        }
    }
}

// ---------------- fp16 tensor-core flash attention (proven) -------------------
#define APH 72
#define FATTN_SMEM (6 * 64 * APH * 2)

extern __shared__ __half attn_smem[];

__global__ __launch_bounds__(128) void fattn_tc(
    const __half* __restrict__ Q, const __half* __restrict__ Kb,
    const __half* __restrict__ Vb, __half* __restrict__ O)
{
    __half* Qs = attn_smem;
    __half* Ks = Qs + 64 * APH;
    __half* Vk = Ks + 2 * 64 * APH;
    __half* Ps = Vk + 2 * 64 * APH;

    const int qt = (gridDim.x - 1) - blockIdx.x;
    const int h  = blockIdx.y, b = blockIdx.z;
    const int q0 = qt * 64;
    const int tid  = threadIdx.x;
    const int lane = tid & 31;
    const int warp = tid >> 5;

    const int OST = Hc * DHc;

    const int r0  = warp * 16 + (lane >> 2);
    const int kh  = (lane & 3) * 2;
    const int ls4 = lane >> 2;

    #pragma unroll
    for (int p = 0; p < 4; p++) {
        int c = tid + p * 128;
        int r = c >> 3, d8 = (c & 7) * 8;
        float4 v = *(const float4*)(Q + (size_t)(b * Sc + q0 + r) * QKVSTR + h * DHc + d8);
        *(float4*)&Qs[r * APH + d8] = v;
    }

    float o_acc[8][4];
    #pragma unroll
    for (int n = 0; n < 8; n++)
        #pragma unroll
        for (int t = 0; t < 4; t++) o_acc[n][t] = 0.f;
    float m0 = -1e30f, m1 = -1e30f, l0 = 0.f, l1 = 0.f;

    const int nt = qt + 1;
    const size_t kvrow0 = (size_t)(b * Sc) * QKVSTR + h * DHc;

    #pragma unroll
    for (int p = 0; p < 4; p++) {
        int c = tid + p * 128;
        int r = c >> 3, d8 = (c & 7) * 8;
        cp16(&Ks[r * APH + d8], Kb + kvrow0 + (size_t)r * QKVSTR + d8, 16);
        cp16(&Vk[r * APH + d8], Vb + kvrow0 + (size_t)r * QKVSTR + d8, 16);
    }
    asm volatile("cp.async.commit_group;\n");

    for (int kt = 0; kt < nt; kt++) {
        asm volatile("cp.async.wait_group 0;\n");
        __syncthreads();

        const int buf = kt & 1;
        if (kt + 1 < nt) {
            const int nb = buf ^ 1;
            const size_t base = kvrow0 + (size_t)(kt + 1) * 64 * QKVSTR;
            #pragma unroll
            for (int p = 0; p < 4; p++) {
                int c = tid + p * 128;
                int r = c >> 3, d8 = (c & 7) * 8;
                cp16(&Ks[nb * 64 * APH + r * APH + d8], Kb + base + (size_t)r * QKVSTR + d8, 16);
                cp16(&Vk[nb * 64 * APH + r * APH + d8], Vb + base + (size_t)r * QKVSTR + d8, 16);
            }
        }
        asm volatile("cp.async.commit_group;\n");

        const __half* Kt = Ks + buf * 64 * APH;
        const __half* Vt = Vk + buf * 64 * APH;

        float sacc[8][4];
        #pragma unroll
        for (int n = 0; n < 8; n++)
            #pragma unroll
            for (int t = 0; t < 4; t++) sacc[n][t] = 0.f;

        #pragma unroll
        for (int ks = 0; ks < 4; ks++) {
            const int kb = ks * 16;
            uint32_t a0 = *(const uint32_t*)&Qs[ r0      * APH + kb + kh];
            uint32_t a1 = *(const uint32_t*)&Qs[(r0 + 8) * APH + kb + kh];
            uint32_t a2 = *(const uint32_t*)&Qs[ r0      * APH + kb + kh + 8];
            uint32_t a3 = *(const uint32_t*)&Qs[(r0 + 8) * APH + kb + kh + 8];
            #pragma unroll
            for (int n = 0; n < 8; n++) {
                const int nr = n * 8 + ls4;
                uint32_t b0 = *(const uint32_t*)&Kt[nr * APH + kb + kh];
                uint32_t b1 = *(const uint32_t*)&Kt[nr * APH + kb + kh + 8];
                mma_f16(sacc[n], a0, a1, a2, a3, b0, b1);
            }
        }

        if (kt == qt) {
            #pragma unroll
            for (int n = 0; n < 8; n++) {
                const int c0 = n * 8 + (lane & 3) * 2;
                if (c0     > r0)     sacc[n][0] = -1e30f;
                if (c0 + 1 > r0)     sacc[n][1] = -1e30f;
                if (c0     > r0 + 8) sacc[n][2] = -1e30f;
                if (c0 + 1 > r0 + 8) sacc[n][3] = -1e30f;
            }
        }

        float mx0 = -1e30f, mx1 = -1e30f;
        #pragma unroll
        for (int n = 0; n < 8; n++) {
            mx0 = fmaxf(mx0, fmaxf(sacc[n][0], sacc[n][1]));
            mx1 = fmaxf(mx1, fmaxf(sacc[n][2], sacc[n][3]));
        }
        mx0 = fmaxf(mx0, __shfl_xor_sync(0xffffffffu, mx0, 1));
        mx0 = fmaxf(mx0, __shfl_xor_sync(0xffffffffu, mx0, 2));
        mx1 = fmaxf(mx1, __shfl_xor_sync(0xffffffffu, mx1, 1));
        mx1 = fmaxf(mx1, __shfl_xor_sync(0xffffffffu, mx1, 2));

        const float mn0 = fmaxf(m0, mx0);
        const float mn1 = fmaxf(m1, mx1);
        const float cr0 = __expf(m0 - mn0);
        const float cr1 = __expf(m1 - mn1);
        float s0 = 0.f, s1 = 0.f;
        #pragma unroll
        for (int n = 0; n < 8; n++) {
            float p00 = __expf(sacc[n][0] - mn0);
            float p01 = __expf(sacc[n][1] - mn0);
            float p10 = __expf(sacc[n][2] - mn1);
            float p11 = __expf(sacc[n][3] - mn1);
            s0 += p00 + p01;
            s1 += p10 + p11;
            const int c0 = n * 8 + (lane & 3) * 2;
            *(__half2*)&Ps[ r0      * APH + c0] = __floats2half2_rn(p00, p01);
            *(__half2*)&Ps[(r0 + 8) * APH + c0] = __floats2half2_rn(p10, p11);
        }
        s0 += __shfl_xor_sync(0xffffffffu, s0, 1);
        s0 += __shfl_xor_sync(0xffffffffu, s0, 2);
        s1 += __shfl_xor_sync(0xffffffffu, s1, 1);
        s1 += __shfl_xor_sync(0xffffffffu, s1, 2);

        l0 = l0 * cr0 + s0;  m0 = mn0;
        l1 = l1 * cr1 + s1;  m1 = mn1;
        #pragma unroll
        for (int n = 0; n < 8; n++) {
            o_acc[n][0] *= cr0; o_acc[n][1] *= cr0;
            o_acc[n][2] *= cr1; o_acc[n][3] *= cr1;
        }
        __syncwarp();

        #pragma unroll
        for (int ks = 0; ks < 4; ks++) {
            const int kb = ks * 16;
            uint32_t a0 = *(const uint32_t*)&Ps[ r0      * APH + kb + kh];
            uint32_t a1 = *(const uint32_t*)&Ps[(r0 + 8) * APH + kb + kh];
            uint32_t a2 = *(const uint32_t*)&Ps[ r0      * APH + kb + kh + 8];
            uint32_t a3 = *(const uint32_t*)&Ps[(r0 + 8) * APH + kb + kh + 8];
            uint32_t base = (uint32_t)__cvta_generic_to_shared(
                                &Vt[(kb + (lane & 15)) * APH]);
            #pragma unroll
            for (int n = 0; n < 8; n++) {
                uint32_t b0, b1;
                ldsm_x2_trans(b0, b1, base + n * 16);
                mma_f16(o_acc[n], a0, a1, a2, a3, b0, b1);
            }
        }
    }

    const float inv0 = 1.f / l0;
    const float inv1 = 1.f / l1;
    #pragma unroll
    for (int n = 0; n < 8; n++) {
        const int c0 = n * 8 + (lane & 3) * 2;
        size_t o0 = (size_t)(b * Sc + q0 + r0)     * OST + h * DHc + c0;
        size_t o1 = (size_t)(b * Sc + q0 + r0 + 8) * OST + h * DHc + c0;
        *(__half2*)&O[o0] = __floats2half2_rn(o_acc[n][0] * inv0, o_acc[n][1] * inv0);
        *(__half2*)&O[o1] = __floats2half2_rn(o_acc[n][2] * inv1, o_acc[n][3] * inv1);
    }
}

// ---------------- LayerNorm over D=512 (float4, dual output) ------------------
__global__ void ln_kernel(const float* __restrict__ X, const float* __restrict__ g,
                          const float* __restrict__ bta, float* __restrict__ Y,
                          __half* __restrict__ Yt) {
    int row = blockIdx.x;
    const float* x = X + (size_t)row * Dc;
    float*  y  = Y  + (size_t)row * Dc;
    __half* yt = Yt + (size_t)row * Dc;
    int tid = threadIdx.x;            // 128 threads, 4 consecutive floats each
    int d0  = tid * 4;

    float4 v = *(const float4*)(x + d0);
    float sum = v.x + v.y + v.z + v.w;

    __shared__ float red[4];
    #pragma unroll
    for (int off = 16; off; off >>= 1) sum += __shfl_xor_sync(0xffffffffu, sum, off);
    if ((tid & 31) == 0) red[tid >> 5] = sum;
    __syncthreads();
    sum = red[0] + red[1] + red[2] + red[3];
    float mean = sum * (1.f / Dc);

    float dx = v.x - mean, dy = v.y - mean, dz = v.z - mean, dw = v.w - mean;
    float sq = dx*dx + dy*dy + dz*dz + dw*dw;
    __shared__ float red2[4];
    #pragma unroll
    for (int off = 16; off; off >>= 1) sq += __shfl_xor_sync(0xffffffffu, sq, off);
    if ((tid & 31) == 0) red2[tid >> 5] = sq;
    __syncthreads();
    sq = red2[0] + red2[1] + red2[2] + red2[3];
    float rstd = rsqrtf(sq * (1.f / Dc) + 1e-5f);

    float4 gg = *(const float4*)(g + d0);
    float4 bb = *(const float4*)(bta + d0);
    float4 o;
    o.x = dx * rstd * gg.x + bb.x;
    o.y = dy * rstd * gg.y + bb.y;
    o.z = dz * rstd * gg.z + bb.z;
    o.w = dw * rstd * gg.w + bb.w;
    *(float4*)(y + d0) = o;
    __half2 ho[2];
    ho[0] = __floats2half2_rn(o.x, o.y);
    ho[1] = __floats2half2_rn(o.z, o.w);
    *(uint2*)(yt + d0) = *(uint2*)ho;
}

// ---------------- launch ----------------------------------------------------
extern "C" void kernel_launch(void* const* d_in, const int* in_sizes, int n_in,
                              void* d_out, int out_size) {
    const int*   data = (const int*)  d_in[0];
    const float* we   = (const float*)d_in[1];
    const float* pe   = (const float*)d_in[2];
    const float* Wq   = (const float*)d_in[3];
    const float* Wkv  = (const float*)d_in[4];
    const float* Wo   = (const float*)d_in[5];
    const float* g1   = (const float*)d_in[6];
    const float* bl1  = (const float*)d_in[7];
    const float* W1   = (const float*)d_in[8];
    const float* bf1  = (const float*)d_in[9];
    const float* W2   = (const float*)d_in[10];
    const float* bf2  = (const float*)d_in[11];
    const float* g2   = (const float*)d_in[12];
    const float* bl2  = (const float*)d_in[13];
    const float* outb = (const float*)d_in[14];
    float* out = (float*)d_out;

    float *h, *tmp;
    __half *ht, *qkv, *aot, *fft;
    __half *wqkv, *wo_t, *w1_t, *w2_t, *we_t;
    cudaGetSymbolAddress((void**)&h,    g_h);
    cudaGetSymbolAddress((void**)&ht,   g_ht);
    cudaGetSymbolAddress((void**)&qkv,  g_qkv);
    cudaGetSymbolAddress((void**)&aot,  g_aot);
    cudaGetSymbolAddress((void**)&tmp,  g_tmp);
    cudaGetSymbolAddress((void**)&fft,  g_fft);
    cudaGetSymbolAddress((void**)&wqkv, g_wqkv);
    cudaGetSymbolAddress((void**)&wo_t, g_wo_t);
    cudaGetSymbolAddress((void**)&w1_t, g_w1_t);
    cudaGetSymbolAddress((void**)&w2_t, g_w2_t);
    cudaGetSymbolAddress((void**)&we_t, g_we_t);

    cudaFuncSetAttribute(fattn_tc, cudaFuncAttributeMaxDynamicSharedMemorySize, FATTN_SMEM);

    {
        int n8;
        n8 = Lc * QKVSTR * Dc / 8;  pack_qkv_w8<<<(n8 + 255)/256, 256>>>(Wq, Wkv, wqkv);
        n8 = Lc * Dc * Dc / 8;      cvt_w8<<<(n8 + 255)/256, 256>>>(Wo, wo_t, n8);
        n8 = Lc * DIc * Dc / 8;     cvt_w8<<<(n8 + 255)/256, 256>>>(W1, w1_t, n8);
        n8 = Lc * Dc * DIc / 8;     cvt_w8<<<(n8 + 255)/256, 256>>>(W2, w2_t, n8);
        n8 = Vc * Dc / 8;           cvt_w8<<<(n8 + 255)/256, 256>>>(we, we_t, n8);
    }

    embed_kernel<<<(M_ROWS*Dc/4 + 255)/256, 256>>>(data, we, pe, h, ht);

    dim3 g64D  ( Dc/128,     M_ROWS/64);    // (4, 64)
    dim3 g64QKV( QKVSTR/128, M_ROWS/64);    // (12, 64)
    dim3 g64DI ( DIc/128,    M_ROWS/64);    // (16, 64)
    dim3 gsV   ((Vc + 127)/128, M_ROWS/128);
    dim3 gsA   (Sc/64, Hc, Bc);

    for (int l = 0; l < Lc; l++) {
        tgemm64_kernel<<<g64QKV, 256>>>(ht, wqkv + (size_t)l*QKVSTR*Dc, nullptr, nullptr,
                                        qkv, M_ROWS, QKVSTR, Dc, 0, 1);

        fattn_tc<<<gsA, 128, FATTN_SMEM>>>(qkv, qkv + Dc, qkv + 2*Dc, aot);

        tgemm64_kernel<<<g64D, 256>>>(aot, wo_t + (size_t)l*Dc*Dc, nullptr, h, tmp,
                                      M_ROWS, Dc, Dc, 0, 0);
        ln_kernel<<<M_ROWS, 128>>>(tmp, g1 + (size_t)l*Dc, bl1 + (size_t)l*Dc, h, ht);

        tgemm64_kernel<<<g64DI, 256>>>(ht, w1_t + (size_t)l*DIc*Dc, bf1 + (size_t)l*DIc, nullptr,
                                       fft, M_ROWS, DIc, Dc, 1, 1);
        tgemm64_kernel<<<g64D, 256>>>(fft, w2_t + (size_t)l*Dc*DIc, bf2 + (size_t)l*Dc, h,
                                      tmp, M_ROWS, Dc, DIc, 0, 0);
        ln_kernel<<<M_ROWS, 128>>>(tmp, g2 + (size_t)l*Dc, bl2 + (size_t)l*Dc, h, ht);
    }

    tgemm_kernel<<<gsV, 256>>>(ht, we_t, outb, nullptr, out, M_ROWS, Vc, Dc, 0, 0);
}